// round 1
// baseline (speedup 1.0000x reference)
#include <cuda_runtime.h>
#include <math.h>

// Problem constants (fixed shapes for this problem)
#define NMAX 100000
#define H 128
#define FIN 256

// -------- scratch (no allocation allowed) --------
__device__ float g_bufA[(size_t)NMAX * H];
__device__ float g_bufB[(size_t)NMAX * H];
__device__ float g_bufC[(size_t)NMAX * H];
__device__ float g_deg[NMAX];
__device__ int   g_is64;

// -------- edge-index dtype detection --------
// If the buffer is int64 (little-endian), every odd 32-bit word is a high half
// and equals 0 (indices < 100000). If int32, odd words are real indices; the
// chance all 1024 samples are zero is (1e-5)^1024 ~ 0.
__global__ void detect_idx64_kernel(const unsigned int* __restrict__ ei) {
    int any = __syncthreads_or(ei[2 * threadIdx.x + 1] != 0u);
    if (threadIdx.x == 0) g_is64 = any ? 0 : 1;
}

__device__ __forceinline__ long long load_idx(const void* ei, long long i, int is64) {
    if (is64) return ((const long long*)ei)[i];
    return (long long)(((const int*)ei)[i]);
}

// -------- zero fill --------
__global__ void zero_kernel(float* __restrict__ p, long long n4) {
    long long i = (long long)blockIdx.x * blockDim.x + threadIdx.x;
    if (i < n4) ((float4*)p)[i] = make_float4(0.f, 0.f, 0.f, 0.f);
}

// -------- degree count (RED, no return) --------
__global__ void deg_kernel(const void* __restrict__ ei, long long E) {
    long long e = (long long)blockIdx.x * blockDim.x + threadIdx.x;
    if (e >= E) return;
    int is64 = g_is64;
    long long dst = load_idx(ei, E + e, is64);
    atomicAdd(&g_deg[dst], 1.0f);
}

__global__ void deginv_kernel(int n) {
    int i = blockIdx.x * blockDim.x + threadIdx.x;
    if (i < n) g_deg[i] = 1.0f / fmaxf(g_deg[i], 1.0f);
}

// -------- scatter-add: agg[dst] += h[src], warp per edge, vector RED --------
__global__ void scatter_kernel(const float* __restrict__ h, float* __restrict__ agg,
                               const void* __restrict__ ei, long long E) {
    long long w = (long long)blockIdx.x * 8 + (threadIdx.x >> 5);  // warp = edge
    int lane = threadIdx.x & 31;
    if (w >= E) return;
    int is64 = g_is64;
    long long src = load_idx(ei, w, is64);
    long long dst = load_idx(ei, E + w, is64);
    float4 v = *(const float4*)(h + src * H + lane * 4);
    float* p = agg + dst * H + lane * 4;
    asm volatile("red.global.add.v4.f32 [%0], {%1, %2, %3, %4};"
                 :: "l"(p), "f"(v.x), "f"(v.y), "f"(v.z), "f"(v.w) : "memory");
}

// -------- generic fused GEMM --------
// C[M,128] = act( A1[M,K1] @ W1[K1,128]  +  (rowscale[m] * A2[M,K2]) @ W2[K2,128]  + bias )
// K1, K2 multiples of 16. A2/W2 may be null (K2 = 0). act: 0 = none, 1 = relu.
// Tile: 64 rows x 128 cols per block, 256 threads, each thread 8x4 outputs.
__global__ void gemm_kernel(const float* __restrict__ A1, int K1, const float* __restrict__ W1,
                            const float* __restrict__ A2, int K2, const float* __restrict__ W2,
                            const float* __restrict__ rowscale,
                            const float* __restrict__ bias, float* __restrict__ C,
                            int M, int act) {
    __shared__ float As[64][16];
    __shared__ float Ws[16][128];

    int t = threadIdx.x;
    int bm = blockIdx.x * 64;
    int warp = t >> 5, lane = t & 31;
    int r0 = warp * 8;        // 8 warps * 8 rows = 64
    int col4 = lane * 4;      // 32 lanes * 4 cols = 128

    // A-load mapping: thread loads one float4 of row la_row
    int la_row = t >> 2;          // 0..63
    int la_k = (t & 3) * 4;       // 0,4,8,12
    int grow = bm + la_row;
    // W-load mapping: thread loads 8 consecutive floats
    int lw_r = t >> 4;            // 0..15
    int lw_c = (t & 15) * 8;      // 0..120

    float acc[8][4];
#pragma unroll
    for (int i = 0; i < 8; i++)
#pragma unroll
        for (int j = 0; j < 4; j++) acc[i][j] = 0.f;

    int KT = K1 + K2;
    for (int kb = 0; kb < KT; kb += 16) {
        // load A tile
        float4 av = make_float4(0.f, 0.f, 0.f, 0.f);
        if (grow < M) {
            if (kb < K1) {
                av = *(const float4*)(A1 + (long long)grow * K1 + (kb + la_k));
            } else {
                av = *(const float4*)(A2 + (long long)grow * K2 + (kb - K1 + la_k));
                float s = rowscale ? rowscale[grow] : 1.0f;
                av.x *= s; av.y *= s; av.z *= s; av.w *= s;
            }
        }
        *(float4*)&As[la_row][la_k] = av;

        // load W tile
        int krow = kb + lw_r;
        const float* wsrc = (krow < K1) ? (W1 + (long long)krow * 128 + lw_c)
                                        : (W2 + (long long)(krow - K1) * 128 + lw_c);
        float4 w0 = *(const float4*)(wsrc);
        float4 w1 = *(const float4*)(wsrc + 4);
        *(float4*)&Ws[lw_r][lw_c] = w0;
        *(float4*)&Ws[lw_r][lw_c + 4] = w1;

        __syncthreads();
#pragma unroll
        for (int kk = 0; kk < 16; kk++) {
            float4 wv = *(float4*)&Ws[kk][col4];
#pragma unroll
            for (int i = 0; i < 8; i++) {
                float a = As[r0 + i][kk];
                acc[i][0] += a * wv.x;
                acc[i][1] += a * wv.y;
                acc[i][2] += a * wv.z;
                acc[i][3] += a * wv.w;
            }
        }
        __syncthreads();
    }

    float4 bv = *(const float4*)(bias + col4);
#pragma unroll
    for (int i = 0; i < 8; i++) {
        int row = bm + r0 + i;
        if (row < M) {
            float4 o;
            o.x = acc[i][0] + bv.x;
            o.y = acc[i][1] + bv.y;
            o.z = acc[i][2] + bv.z;
            o.w = acc[i][3] + bv.w;
            if (act) {
                o.x = fmaxf(o.x, 0.f); o.y = fmaxf(o.y, 0.f);
                o.z = fmaxf(o.z, 0.f); o.w = fmaxf(o.w, 0.f);
            }
            *(float4*)(C + (long long)row * 128 + col4) = o;
        }
    }
}

// -------- dist path layer0: y0 = relu(e[N,5] @ W0[5,128] + b0) --------
__global__ void dist0_kernel(const float* __restrict__ e, const float* __restrict__ W0,
                             const float* __restrict__ b0, float* __restrict__ out, int n) {
    __shared__ float sW[5 * 128];
    __shared__ float sb[128];
    int t = threadIdx.x;  // 128
    for (int i = t; i < 5 * 128; i += 128) sW[i] = W0[i];
    sb[t] = b0[t];
    __syncthreads();
    for (long long nd = blockIdx.x; nd < n; nd += gridDim.x) {
        const float* ev = e + nd * 5;
        float v = sb[t];
        v += ev[0] * sW[0 * 128 + t];
        v += ev[1] * sW[1 * 128 + t];
        v += ev[2] * sW[2 * 128 + t];
        v += ev[3] * sW[3 * 128 + t];
        v += ev[4] * sW[4 * 128 + t];
        out[nd * 128 + t] = fmaxf(v, 0.f);
    }
}

// -------- final: out[n] = sigmoid(feat . fW[0:128] + dist . fW[128:256] + fb) --------
__global__ void final_kernel(const float* __restrict__ feat, const float* __restrict__ dist,
                             const float* __restrict__ fW, const float* __restrict__ fb,
                             float* __restrict__ out, int n) {
    long long wg = (long long)blockIdx.x * 8 + (threadIdx.x >> 5);
    int lane = threadIdx.x & 31;
    if (wg >= n) return;
    float4 f = *(const float4*)(feat + wg * 128 + lane * 4);
    float4 w1 = *(const float4*)(fW + lane * 4);
    float4 d = *(const float4*)(dist + wg * 128 + lane * 4);
    float4 w2 = *(const float4*)(fW + 128 + lane * 4);
    float s = f.x * w1.x + f.y * w1.y + f.z * w1.z + f.w * w1.w
            + d.x * w2.x + d.y * w2.y + d.z * w2.z + d.w * w2.w;
#pragma unroll
    for (int off = 16; off; off >>= 1) s += __shfl_xor_sync(0xFFFFFFFFu, s, off);
    if (lane == 0) {
        float z = s + fb[0];
        out[wg] = 1.0f / (1.0f + expf(-z));
    }
}

extern "C" void kernel_launch(void* const* d_in, const int* in_sizes, int n_in,
                              void* d_out, int out_size) {
    const float* x          = (const float*)d_in[0];
    const void*  ei         = d_in[1];
    const float* eattr      = (const float*)d_in[2];
    const float* pre_W      = (const float*)d_in[3];
    const float* pre_b      = (const float*)d_in[4];
    const float* c1_Ws      = (const float*)d_in[5];
    const float* c1_Wn      = (const float*)d_in[6];
    const float* c1_b       = (const float*)d_in[7];
    const float* c2_Ws      = (const float*)d_in[8];
    const float* c2_Wn      = (const float*)d_in[9];
    const float* c2_b       = (const float*)d_in[10];
    const float* nodepost_W = (const float*)d_in[11];
    const float* nodepost_b = (const float*)d_in[12];
    const float* d_W0       = (const float*)d_in[13];
    const float* d_b0       = (const float*)d_in[14];
    const float* d_W1       = (const float*)d_in[15];
    const float* d_b1       = (const float*)d_in[16];
    const float* d_W2       = (const float*)d_in[17];
    const float* d_b2       = (const float*)d_in[18];
    const float* d_W3       = (const float*)d_in[19];
    const float* d_b3       = (const float*)d_in[20];
    const float* final_W    = (const float*)d_in[21];
    const float* final_b    = (const float*)d_in[22];
    float* out = (float*)d_out;

    int n = in_sizes[0] / FIN;
    long long E = (long long)in_sizes[1] / 2;

    float *bufA, *bufB, *bufC, *deg;
    cudaGetSymbolAddress((void**)&bufA, g_bufA);
    cudaGetSymbolAddress((void**)&bufB, g_bufB);
    cudaGetSymbolAddress((void**)&bufC, g_bufC);
    cudaGetSymbolAddress((void**)&deg, g_deg);

    long long nh4 = ((long long)n * H) / 4;
    int gemm_grid = (n + 63) / 64;
    int scat_grid = (int)((E + 7) / 8);

    // edge index dtype
    detect_idx64_kernel<<<1, 1024>>>((const unsigned int*)ei);

    // degree -> 1/max(deg,1)
    zero_kernel<<<(int)((n / 4 + 255) / 256) + 1, 256>>>(deg, (n + 3) / 4);
    deg_kernel<<<(int)((E + 255) / 256), 256>>>(ei, E);
    deginv_kernel<<<(n + 255) / 256, 256>>>(n);

    // pre: h0 = x @ pre_W + pre_b          -> bufA
    gemm_kernel<<<gemm_grid, 256>>>(x, FIN, pre_W, nullptr, 0, nullptr, nullptr,
                                    pre_b, bufA, n, 0);

    // agg1 = scatter(h0)                   -> bufB
    zero_kernel<<<(int)((nh4 + 255) / 256), 256>>>(bufB, nh4);
    scatter_kernel<<<scat_grid, 256>>>(bufA, bufB, ei, E);

    // h1 = relu(h0@c1_Ws + deginv*agg1@c1_Wn + b) -> bufC
    gemm_kernel<<<gemm_grid, 256>>>(bufA, H, c1_Ws, bufB, H, c1_Wn, deg,
                                    c1_b, bufC, n, 1);

    // agg2 = scatter(h1)                   -> bufB
    zero_kernel<<<(int)((nh4 + 255) / 256), 256>>>(bufB, nh4);
    scatter_kernel<<<scat_grid, 256>>>(bufC, bufB, ei, E);

    // h2 = relu(h1@c2_Ws + deginv*agg2@c2_Wn + b) -> bufA
    gemm_kernel<<<gemm_grid, 256>>>(bufC, H, c2_Ws, bufB, H, c2_Wn, deg,
                                    c2_b, bufA, n, 1);

    // feat = h2 @ nodepost_W + b           -> bufC
    gemm_kernel<<<gemm_grid, 256>>>(bufA, H, nodepost_W, nullptr, 0, nullptr, nullptr,
                                    nodepost_b, bufC, n, 0);

    // dist path: y0 -> bufB, y1 -> bufA, y2 -> bufB, y3 -> bufA
    dist0_kernel<<<2048, 128>>>(eattr, d_W0, d_b0, bufB, n);
    gemm_kernel<<<gemm_grid, 256>>>(bufB, H, d_W1, nullptr, 0, nullptr, nullptr,
                                    d_b1, bufA, n, 1);
    gemm_kernel<<<gemm_grid, 256>>>(bufA, H, d_W2, nullptr, 0, nullptr, nullptr,
                                    d_b2, bufB, n, 1);
    gemm_kernel<<<gemm_grid, 256>>>(bufB, H, d_W3, nullptr, 0, nullptr, nullptr,
                                    d_b3, bufA, n, 0);

    // final: sigmoid(feat.fW1 + y3.fW2 + fb)
    final_kernel<<<(n + 7) / 8, 256>>>(bufC, bufA, final_W, final_b, out, n);
}

// round 4
// speedup vs baseline: 1.2633x; 1.2633x over previous
#include <cuda_runtime.h>
#include <math.h>
#include <cstdint>

// Problem constants (fixed shapes for this problem)
#define NMAX 100000
#define H 128
#define FIN 256

// -------- scratch (no allocation allowed) --------
__device__ float g_bufA[(size_t)NMAX * H];
__device__ float g_bufB[(size_t)NMAX * H];
__device__ float g_bufC[(size_t)NMAX * H];
__device__ float g_deg[NMAX];
__device__ float g_wbuf[32768 + 8 * 16384];   // rearranged weight fragments
__device__ int   g_is64;

// ================ edge-index dtype detection ================
// If the buffer is int64 (little-endian), every odd 32-bit word is a high half
// and equals 0 (indices < 100000). If int32, odd words are real indices.
__global__ void detect_idx64_kernel(const unsigned int* __restrict__ ei) {
    int any = __syncthreads_or(ei[2 * threadIdx.x + 1] != 0u);
    if (threadIdx.x == 0) g_is64 = any ? 0 : 1;
}
__device__ __forceinline__ long long load_idx(const void* ei, long long i, int is64) {
    if (is64) return ((const long long*)ei)[i];
    return (long long)(((const int*)ei)[i]);
}

// ================ small kernels ================
__global__ void zero_kernel(float* __restrict__ p, long long n4) {
    long long i = (long long)blockIdx.x * blockDim.x + threadIdx.x;
    if (i < n4) ((float4*)p)[i] = make_float4(0.f, 0.f, 0.f, 0.f);
}
__global__ void deg_kernel(const void* __restrict__ ei, long long E) {
    long long e = (long long)blockIdx.x * blockDim.x + threadIdx.x;
    if (e >= E) return;
    int is64 = g_is64;
    long long dst = load_idx(ei, E + e, is64);
    atomicAdd(&g_deg[dst], 1.0f);
}
__global__ void deginv_kernel(int n) {
    int i = blockIdx.x * blockDim.x + threadIdx.x;
    if (i < n) g_deg[i] = 1.0f / fmaxf(g_deg[i], 1.0f);
}

// scatter-add: agg[dst] += h[src], warp per edge, vector RED
__global__ void scatter_kernel(const float* __restrict__ h, float* __restrict__ agg,
                               const void* __restrict__ ei, long long E) {
    long long w = (long long)blockIdx.x * 8 + (threadIdx.x >> 5);
    int lane = threadIdx.x & 31;
    if (w >= E) return;
    int is64 = g_is64;
    long long src = load_idx(ei, w, is64);
    long long dst = load_idx(ei, E + w, is64);
    float4 v = *(const float4*)(h + src * H + lane * 4);
    float* p = agg + dst * H + lane * 4;
    asm volatile("red.global.add.v4.f32 [%0], {%1, %2, %3, %4};"
                 :: "l"(p), "f"(v.x), "f"(v.y), "f"(v.z), "f"(v.w) : "memory");
}

// ================ tf32 helpers ================
__device__ __forceinline__ uint32_t to_tf32(float f) {
    uint32_t r;
    asm("cvt.rna.tf32.f32 %0, %1;" : "=r"(r) : "f"(f));
    return r;
}
__device__ __forceinline__ void mma_tf32(float* c, uint32_t a0, uint32_t a1,
                                         uint32_t a2, uint32_t a3,
                                         uint32_t b0, uint32_t b1) {
    asm volatile(
        "mma.sync.aligned.m16n8k8.row.col.f32.tf32.tf32.f32 "
        "{%0,%1,%2,%3}, {%4,%5,%6,%7}, {%8,%9}, {%0,%1,%2,%3};"
        : "+f"(c[0]), "+f"(c[1]), "+f"(c[2]), "+f"(c[3])
        : "r"(a0), "r"(a1), "r"(a2), "r"(a3), "r"(b0), "r"(b1));
}

// ================ weight fragment preparation ================
// Rearrange W[K][128] into mma B-fragment order:
//   float2 out[kstep][ntile][lane] with
//   b0 = W[kstep*8 + (lane&3)]    [ntile*8 + (lane>>2)]
//   b1 = W[kstep*8 + (lane&3) + 4][ntile*8 + (lane>>2)]
// both tf32-rounded. One thread per output float2.
__global__ void prepW_kernel(const float* __restrict__ W, float* __restrict__ dst, int K) {
    int idx = blockIdx.x * blockDim.x + threadIdx.x;
    int total = (K >> 3) * 16 * 32;
    if (idx >= total) return;
    int lane = idx & 31;
    int ntile = (idx >> 5) & 15;
    int kstep = idx >> 9;
    int k0 = kstep * 8 + (lane & 3);
    int n = ntile * 8 + (lane >> 2);
    uint32_t b0 = to_tf32(W[k0 * 128 + n]);
    uint32_t b1 = to_tf32(W[(k0 + 4) * 128 + n]);
    ((uint2*)dst)[idx] = make_uint2(b0, b1);
}

// ================ tensor-core fused GEMM (mma.sync tf32) ================
// C[M,128] = act( A1[M,K1]@W1 + (rowscale ⊙ A2[M,K2])@W2 + bias )
// Wf1/Wf2 are PRE-ARRANGED fragment buffers (prepW_kernel output).
// CTA: 128 rows x 128 cols, 256 threads, warp tile 32x64.
// Dynamic SMEM: Wfrags[(K1+K2)*128] floats + Apanel[128][20] + bias[128].
#define APAD 20

__global__ void __launch_bounds__(256, 1)
tc_gemm(const float* __restrict__ A1, int K1, const float* __restrict__ Wf1,
        const float* __restrict__ A2, int K2, const float* __restrict__ Wf2,
        const float* __restrict__ rowscale, const float* __restrict__ bias,
        float* __restrict__ C, int M, int act) {
    extern __shared__ float smem[];
    int KT = K1 + K2;
    float* sW = smem;                     // KT*128 floats (fragment order)
    float* sA = smem + (size_t)KT * 128;  // 128*APAD floats
    float* sB = sA + 128 * APAD;          // 128 floats bias

    int t = threadIdx.x, warp = t >> 5, lane = t & 31;
    int bm = blockIdx.x * 128;
    int wm = (warp & 3) * 32;   // warp row offset
    int wn = (warp >> 2) * 64;  // warp col offset

    // copy weight fragments to SMEM (coalesced float4)
    {
        const float4* s1 = (const float4*)Wf1;
        float4* d = (float4*)sW;
        for (int i = t; i < K1 * 32; i += 256) d[i] = s1[i];
        if (K2 > 0) {
            const float4* s2 = (const float4*)Wf2;
            float4* d2 = (float4*)(sW + (size_t)K1 * 128);
            for (int i = t; i < K2 * 32; i += 256) d2[i] = s2[i];
        }
        if (t < 128) sB[t] = bias[t];
    }

    float acc[2][8][4];
#pragma unroll
    for (int a = 0; a < 2; a++)
#pragma unroll
        for (int b = 0; b < 8; b++)
#pragma unroll
            for (int c = 0; c < 4; c++) acc[a][b][c] = 0.f;

    int nPanels = KT >> 4;
    for (int p = 0; p < nPanels; p++) {
        const float* Asrc; int Ak, kp; bool scaled;
        if (p * 16 < K1) { Asrc = A1; Ak = K1; kp = p * 16; scaled = false; }
        else             { Asrc = A2; Ak = K2; kp = p * 16 - K1; scaled = true; }

        __syncthreads();
        // load A panel [128 rows][16 k] -> sA padded, tf32-rounded
#pragma unroll
        for (int j = 0; j < 2; j++) {
            int idx = t + j * 256;          // 0..511
            int row = idx >> 2;             // 0..127
            int c4 = (idx & 3) * 4;
            int grow = bm + row;
            float4 v = make_float4(0.f, 0.f, 0.f, 0.f);
            if (grow < M) {
                v = *(const float4*)(Asrc + (size_t)grow * Ak + kp + c4);
                if (scaled) {
                    float s = rowscale ? rowscale[grow] : 1.0f;
                    v.x *= s; v.y *= s; v.z *= s; v.w *= s;
                }
            }
            uint32_t* st = (uint32_t*)(sA + row * APAD + c4);
            st[0] = to_tf32(v.x); st[1] = to_tf32(v.y);
            st[2] = to_tf32(v.z); st[3] = to_tf32(v.w);
        }
        __syncthreads();

#pragma unroll
        for (int ks = 0; ks < 2; ks++) {
            int kk = p * 16 + ks * 8;  // global k of this kstep
            // B fragments: one LDS.64 per ntile, conflict-free
            uint2 bf[8];
            const uint2* wf = ((const uint2*)sW) + ((size_t)(kk >> 3) * 16 + (wn >> 3)) * 32 + lane;
#pragma unroll
            for (int j = 0; j < 8; j++) bf[j] = wf[j * 32];

#pragma unroll
            for (int mt = 0; mt < 2; mt++) {
                int r = wm + mt * 16 + (lane >> 2);
                int c = ks * 8 + (lane & 3);
                uint32_t a0 = ((uint32_t*)sA)[r * APAD + c];
                uint32_t a1 = ((uint32_t*)sA)[(r + 8) * APAD + c];
                uint32_t a2 = ((uint32_t*)sA)[r * APAD + c + 4];
                uint32_t a3 = ((uint32_t*)sA)[(r + 8) * APAD + c + 4];
#pragma unroll
                for (int nt = 0; nt < 8; nt++)
                    mma_tf32(acc[mt][nt], a0, a1, a2, a3, bf[nt].x, bf[nt].y);
            }
        }
    }

    // epilogue: bias + relu, direct float2 stores
#pragma unroll
    for (int mt = 0; mt < 2; mt++) {
        int r0 = bm + wm + mt * 16 + (lane >> 2);
#pragma unroll
        for (int nt = 0; nt < 8; nt++) {
            int col = wn + nt * 8 + (lane & 3) * 2;
            float b0 = sB[col], b1 = sB[col + 1];
            float v0 = acc[mt][nt][0] + b0;
            float v1 = acc[mt][nt][1] + b1;
            float v2 = acc[mt][nt][2] + b0;
            float v3 = acc[mt][nt][3] + b1;
            if (act) {
                v0 = fmaxf(v0, 0.f); v1 = fmaxf(v1, 0.f);
                v2 = fmaxf(v2, 0.f); v3 = fmaxf(v3, 0.f);
            }
            if (r0 < M)     *(float2*)(C + (size_t)r0 * 128 + col)       = make_float2(v0, v1);
            if (r0 + 8 < M) *(float2*)(C + (size_t)(r0 + 8) * 128 + col) = make_float2(v2, v3);
        }
    }
}

// -------- dist path layer0: y0 = relu(e[N,5] @ W0[5,128] + b0) --------
__global__ void dist0_kernel(const float* __restrict__ e, const float* __restrict__ W0,
                             const float* __restrict__ b0, float* __restrict__ out, int n) {
    __shared__ float sW[5 * 128];
    __shared__ float sb[128];
    int t = threadIdx.x;  // 128
    for (int i = t; i < 5 * 128; i += 128) sW[i] = W0[i];
    sb[t] = b0[t];
    __syncthreads();
    for (long long nd = blockIdx.x; nd < n; nd += gridDim.x) {
        const float* ev = e + nd * 5;
        float v = sb[t];
        v += ev[0] * sW[0 * 128 + t];
        v += ev[1] * sW[1 * 128 + t];
        v += ev[2] * sW[2 * 128 + t];
        v += ev[3] * sW[3 * 128 + t];
        v += ev[4] * sW[4 * 128 + t];
        out[nd * 128 + t] = fmaxf(v, 0.f);
    }
}

// -------- final: out[n] = sigmoid(feat.fW[0:128] + dist.fW[128:256] + fb) --------
__global__ void final_kernel(const float* __restrict__ feat, const float* __restrict__ dist,
                             const float* __restrict__ fW, const float* __restrict__ fb,
                             float* __restrict__ out, int n) {
    long long wg = (long long)blockIdx.x * 8 + (threadIdx.x >> 5);
    int lane = threadIdx.x & 31;
    if (wg >= n) return;
    float4 f = *(const float4*)(feat + wg * 128 + lane * 4);
    float4 w1 = *(const float4*)(fW + lane * 4);
    float4 d = *(const float4*)(dist + wg * 128 + lane * 4);
    float4 w2 = *(const float4*)(fW + 128 + lane * 4);
    float s = f.x * w1.x + f.y * w1.y + f.z * w1.z + f.w * w1.w
            + d.x * w2.x + d.y * w2.y + d.z * w2.z + d.w * w2.w;
#pragma unroll
    for (int off = 16; off; off >>= 1) s += __shfl_xor_sync(0xFFFFFFFFu, s, off);
    if (lane == 0) {
        float z = s + fb[0];
        out[wg] = 1.0f / (1.0f + expf(-z));
    }
}

extern "C" void kernel_launch(void* const* d_in, const int* in_sizes, int n_in,
                              void* d_out, int out_size) {
    const float* x          = (const float*)d_in[0];
    const void*  ei         = d_in[1];
    const float* eattr      = (const float*)d_in[2];
    const float* pre_W      = (const float*)d_in[3];
    const float* pre_b      = (const float*)d_in[4];
    const float* c1_Ws      = (const float*)d_in[5];
    const float* c1_Wn      = (const float*)d_in[6];
    const float* c1_b       = (const float*)d_in[7];
    const float* c2_Ws      = (const float*)d_in[8];
    const float* c2_Wn      = (const float*)d_in[9];
    const float* c2_b       = (const float*)d_in[10];
    const float* nodepost_W = (const float*)d_in[11];
    const float* nodepost_b = (const float*)d_in[12];
    const float* d_W0       = (const float*)d_in[13];
    const float* d_b0       = (const float*)d_in[14];
    const float* d_W1       = (const float*)d_in[15];
    const float* d_b1       = (const float*)d_in[16];
    const float* d_W2       = (const float*)d_in[17];
    const float* d_b2       = (const float*)d_in[18];
    const float* d_W3       = (const float*)d_in[19];
    const float* d_b3       = (const float*)d_in[20];
    const float* final_W    = (const float*)d_in[21];
    const float* final_b    = (const float*)d_in[22];
    float* out = (float*)d_out;

    int n = in_sizes[0] / FIN;
    long long E = (long long)in_sizes[1] / 2;

    float *bufA, *bufB, *bufC, *deg, *wbuf;
    cudaGetSymbolAddress((void**)&bufA, g_bufA);
    cudaGetSymbolAddress((void**)&bufB, g_bufB);
    cudaGetSymbolAddress((void**)&bufC, g_bufC);
    cudaGetSymbolAddress((void**)&deg, g_deg);
    cudaGetSymbolAddress((void**)&wbuf, g_wbuf);

    // fragment buffer layout
    float* f_pre  = wbuf;                  // 256x128 -> 32768
    float* f_c1s  = wbuf + 32768;
    float* f_c1n  = f_c1s + 16384;
    float* f_c2s  = f_c1n + 16384;
    float* f_c2n  = f_c2s + 16384;
    float* f_np   = f_c2n + 16384;
    float* f_d1   = f_np + 16384;
    float* f_d2   = f_d1 + 16384;
    float* f_d3   = f_d2 + 16384;

    // No static guards (harness forbids them) — set the attribute every call.
    const int SMEM_K256 = (256 * 128 + 128 * APAD + 128) * 4;
    const int SMEM_K128 = (128 * 128 + 128 * APAD + 128) * 4;
    cudaFuncSetAttribute(tc_gemm, cudaFuncAttributeMaxDynamicSharedMemorySize, SMEM_K256);

    long long nh4 = ((long long)n * H) / 4;
    int gemm_grid = (n + 127) / 128;
    int scat_grid = (int)((E + 7) / 8);

    detect_idx64_kernel<<<1, 1024>>>((const unsigned int*)ei);

    // weight fragment prep (9 small launches, ~µs total)
    prepW_kernel<<<(16384 + 255) / 256, 256>>>(pre_W, f_pre, 256);
    prepW_kernel<<<(8192 + 255) / 256, 256>>>(c1_Ws, f_c1s, 128);
    prepW_kernel<<<(8192 + 255) / 256, 256>>>(c1_Wn, f_c1n, 128);
    prepW_kernel<<<(8192 + 255) / 256, 256>>>(c2_Ws, f_c2s, 128);
    prepW_kernel<<<(8192 + 255) / 256, 256>>>(c2_Wn, f_c2n, 128);
    prepW_kernel<<<(8192 + 255) / 256, 256>>>(nodepost_W, f_np, 128);
    prepW_kernel<<<(8192 + 255) / 256, 256>>>(d_W1, f_d1, 128);
    prepW_kernel<<<(8192 + 255) / 256, 256>>>(d_W2, f_d2, 128);
    prepW_kernel<<<(8192 + 255) / 256, 256>>>(d_W3, f_d3, 128);

    zero_kernel<<<(int)((n / 4 + 255) / 256) + 1, 256>>>(deg, (n + 3) / 4);
    deg_kernel<<<(int)((E + 255) / 256), 256>>>(ei, E);
    deginv_kernel<<<(n + 255) / 256, 256>>>(n);

    // pre: h0 = x @ pre_W + pre_b  -> bufA
    tc_gemm<<<gemm_grid, 256, SMEM_K256>>>(x, FIN, f_pre, nullptr, 0, nullptr, nullptr,
                                           pre_b, bufA, n, 0);

    // agg1 = scatter(h0) -> bufB
    zero_kernel<<<(int)((nh4 + 255) / 256), 256>>>(bufB, nh4);
    scatter_kernel<<<scat_grid, 256>>>(bufA, bufB, ei, E);

    // h1 = relu(h0@c1_Ws + deginv*agg1@c1_Wn + b) -> bufC
    tc_gemm<<<gemm_grid, 256, SMEM_K256>>>(bufA, H, f_c1s, bufB, H, f_c1n, deg,
                                           c1_b, bufC, n, 1);

    // agg2 = scatter(h1) -> bufB
    zero_kernel<<<(int)((nh4 + 255) / 256), 256>>>(bufB, nh4);
    scatter_kernel<<<scat_grid, 256>>>(bufC, bufB, ei, E);

    // h2 = relu(h1@c2_Ws + deginv*agg2@c2_Wn + b) -> bufA
    tc_gemm<<<gemm_grid, 256, SMEM_K256>>>(bufC, H, f_c2s, bufB, H, f_c2n, deg,
                                           c2_b, bufA, n, 1);

    // feat = h2 @ nodepost_W + b -> bufC
    tc_gemm<<<gemm_grid, 256, SMEM_K128>>>(bufA, H, f_np, nullptr, 0, nullptr, nullptr,
                                           nodepost_b, bufC, n, 0);

    // dist path: y0 -> bufB, then 3 GEMMs ping-pong
    dist0_kernel<<<2048, 128>>>(eattr, d_W0, d_b0, bufB, n);
    tc_gemm<<<gemm_grid, 256, SMEM_K128>>>(bufB, H, f_d1, nullptr, 0, nullptr, nullptr,
                                           d_b1, bufA, n, 1);
    tc_gemm<<<gemm_grid, 256, SMEM_K128>>>(bufA, H, f_d2, nullptr, 0, nullptr, nullptr,
                                           d_b2, bufB, n, 1);
    tc_gemm<<<gemm_grid, 256, SMEM_K128>>>(bufB, H, f_d3, nullptr, 0, nullptr, nullptr,
                                           d_b3, bufA, n, 0);

    final_kernel<<<(n + 7) / 8, 256>>>(bufC, bufA, final_W, final_b, out, n);
}

// round 8
// speedup vs baseline: 1.6041x; 1.2698x over previous
#include <cuda_runtime.h>
#include <math.h>
#include <cstdint>

// Problem constants (fixed shapes for this problem)
#define NMAX 100000
#define H 128
#define FIN 256

// -------- scratch (no allocation allowed) --------
__device__ float g_bufA[(size_t)NMAX * H];
__device__ float g_bufB[(size_t)NMAX * H];
__device__ float g_bufC[(size_t)NMAX * H];
__device__ float g_deg[NMAX];
__device__ float g_wbuf[32768 + 8 * 16384];   // rearranged weight fragments
__device__ int   g_is64;

// ================ edge-index dtype detection ================
__global__ void detect_idx64_kernel(const unsigned int* __restrict__ ei) {
    int any = __syncthreads_or(ei[2 * threadIdx.x + 1] != 0u);
    if (threadIdx.x == 0) g_is64 = any ? 0 : 1;
}
__device__ __forceinline__ long long load_idx(const void* ei, long long i, int is64) {
    if (is64) return ((const long long*)ei)[i];
    return (long long)(((const int*)ei)[i]);
}

// ================ small kernels ================
__global__ void zero_kernel(float* __restrict__ p, long long n4) {
    long long i = (long long)blockIdx.x * blockDim.x + threadIdx.x;
    if (i < n4) ((float4*)p)[i] = make_float4(0.f, 0.f, 0.f, 0.f);
}
__global__ void deg_kernel(const void* __restrict__ ei, long long E) {
    long long e = (long long)blockIdx.x * blockDim.x + threadIdx.x;
    if (e >= E) return;
    int is64 = g_is64;
    long long dst = load_idx(ei, E + e, is64);
    atomicAdd(&g_deg[dst], 1.0f);
}
__global__ void deginv_kernel(int n) {
    int i = blockIdx.x * blockDim.x + threadIdx.x;
    if (i < n) g_deg[i] = 1.0f / fmaxf(g_deg[i], 1.0f);
}

// scatter-add: agg[dst] += h[src], warp per edge, vector RED
__global__ void scatter_kernel(const float* __restrict__ h, float* __restrict__ agg,
                               const void* __restrict__ ei, long long E) {
    long long w = (long long)blockIdx.x * 8 + (threadIdx.x >> 5);
    int lane = threadIdx.x & 31;
    if (w >= E) return;
    int is64 = g_is64;
    long long src = load_idx(ei, w, is64);
    long long dst = load_idx(ei, E + w, is64);
    float4 v = *(const float4*)(h + src * H + lane * 4);
    float* p = agg + dst * H + lane * 4;
    asm volatile("red.global.add.v4.f32 [%0], {%1, %2, %3, %4};"
                 :: "l"(p), "f"(v.x), "f"(v.y), "f"(v.z), "f"(v.w) : "memory");
}

// ================ tf32 helpers ================
__device__ __forceinline__ uint32_t to_tf32(float f) {
    uint32_t r;
    asm("cvt.rna.tf32.f32 %0, %1;" : "=r"(r) : "f"(f));
    return r;
}
__device__ __forceinline__ void mma_tf32(float* c, uint32_t a0, uint32_t a1,
                                         uint32_t a2, uint32_t a3,
                                         uint32_t b0, uint32_t b1) {
    asm volatile(
        "mma.sync.aligned.m16n8k8.row.col.f32.tf32.tf32.f32 "
        "{%0,%1,%2,%3}, {%4,%5,%6,%7}, {%8,%9}, {%0,%1,%2,%3};"
        : "+f"(c[0]), "+f"(c[1]), "+f"(c[2]), "+f"(c[3])
        : "r"(a0), "r"(a1), "r"(a2), "r"(a3), "r"(b0), "r"(b1));
}

// ================ weight fragment preparation ================
// float2 out[kstep][ntile][lane]:
//   b0 = W[kstep*8 + (lane&3)]    [ntile*8 + (lane>>2)]
//   b1 = W[kstep*8 + (lane&3) + 4][ntile*8 + (lane>>2)], tf32-rounded.
__global__ void prepW_kernel(const float* __restrict__ W, float* __restrict__ dst, int K) {
    int idx = blockIdx.x * blockDim.x + threadIdx.x;
    int total = (K >> 3) * 16 * 32;
    if (idx >= total) return;
    int lane = idx & 31;
    int ntile = (idx >> 5) & 15;
    int kstep = idx >> 9;
    int k0 = kstep * 8 + (lane & 3);
    int n = ntile * 8 + (lane >> 2);
    uint32_t b0 = to_tf32(W[k0 * 128 + n]);
    uint32_t b1 = to_tf32(W[(k0 + 4) * 128 + n]);
    ((uint2*)dst)[idx] = make_uint2(b0, b1);
}

// ================ persistent tensor-core GEMM (register double-buffered) ================
// C[M,128] = act( A1[M,K1]@W1 + (rowscale ⊙ A2[M,K2])@W2 + bias )
// Persistent CTAs: weight fragments + bias loaded to SMEM ONCE per CTA;
// M-blocks strided by gridDim. A panel = 128 rows x 32 k, single SMEM buffer.
// FULL panel coverage: 1024 float4 chunks, 4 per thread:
//   row = (t>>3) + j*32 (j=0..3), float-col = (t&7)*4  -> all 32 columns.
// Next panel prefetched into registers while current panel's mma runs.
#define AROW 36
#define ABUF (128 * AROW)

__global__ void __launch_bounds__(256)
tc_gemm(const float* __restrict__ A1, int K1, const float* __restrict__ Wf1,
        const float* __restrict__ A2, int K2, const float* __restrict__ Wf2,
        const float* __restrict__ rowscale, const float* __restrict__ bias,
        float* __restrict__ C, int M, int act) {
    extern __shared__ float smem[];
    int KT = K1 + K2;
    float* sW = smem;                         // KT*128 floats (fragment order)
    float* sA = smem + (size_t)KT * 128;      // ABUF floats
    float* sB = sA + ABUF;                    // 128 floats bias

    int t = threadIdx.x, warp = t >> 5, lane = t & 31;
    int wm = (warp & 3) * 32;   // warp row offset
    int wn = (warp >> 2) * 64;  // warp col offset
    bool haveScale = (rowscale != nullptr);

    // one-time: weight fragments + bias to SMEM
    {
        const float4* s1 = (const float4*)Wf1;
        float4* d = (float4*)sW;
        for (int i = t; i < K1 * 32; i += 256) d[i] = s1[i];
        if (K2 > 0) {
            const float4* s2 = (const float4*)Wf2;
            float4* d2 = (float4*)(sW + (size_t)K1 * 128);
            for (int i = t; i < K2 * 32; i += 256) d2[i] = s2[i];
        }
        if (t < 128) sB[t] = bias[t];
    }
    __syncthreads();

    int nMB = (M + 127) >> 7;
    int nP = KT >> 5;

    // panel-load mapping: 1024 float4 chunks, 4 per thread (FULL 128x32 panel)
    int lrow = t >> 3;         // 0..31, actual rows lrow + j*32
    int lc4 = (t & 7) * 4;     // float offset 0..28 within 32-wide panel

    for (int mb = blockIdx.x; mb < nMB; mb += gridDim.x) {
        int bm = mb << 7;

        float acc[2][8][4];
#pragma unroll
        for (int a = 0; a < 2; a++)
#pragma unroll
            for (int b = 0; b < 8; b++)
#pragma unroll
                for (int c = 0; c < 4; c++) acc[a][b][c] = 0.f;

        // prefetch panel 0 into registers
        float4 rv[4];
        {
            const float* Asrc = A1; int Ak = K1; bool sc = false;
            if (K1 == 0) { Asrc = A2; Ak = K2; sc = haveScale; }
#pragma unroll
            for (int j = 0; j < 4; j++) {
                int row = lrow + j * 32;
                int grow = bm + row;
                float4 v = make_float4(0.f, 0.f, 0.f, 0.f);
                if (grow < M) {
                    v = *(const float4*)(Asrc + (size_t)grow * Ak + lc4);
                    if (sc) { float s = rowscale[grow]; v.x *= s; v.y *= s; v.z *= s; v.w *= s; }
                }
                rv[j] = v;
            }
        }

        for (int p = 0; p < nP; p++) {
            __syncthreads();   // previous panel's mma done -> sA free
            // store prefetched regs to SMEM (tf32-rounded)
#pragma unroll
            for (int j = 0; j < 4; j++) {
                int row = lrow + j * 32;
                uint32_t* st = (uint32_t*)(sA + row * AROW + lc4);
                st[0] = to_tf32(rv[j].x); st[1] = to_tf32(rv[j].y);
                st[2] = to_tf32(rv[j].z); st[3] = to_tf32(rv[j].w);
            }
            __syncthreads();   // panel visible

            // prefetch next panel into registers (LDG latency hidden by mma below)
            if (p + 1 < nP) {
                int kt = (p + 1) << 5;
                const float* Asrc; int Ak, kp; bool sc;
                if (kt < K1) { Asrc = A1; Ak = K1; kp = kt; sc = false; }
                else         { Asrc = A2; Ak = K2; kp = kt - K1; sc = haveScale; }
#pragma unroll
                for (int j = 0; j < 4; j++) {
                    int row = lrow + j * 32;
                    int grow = bm + row;
                    float4 v = make_float4(0.f, 0.f, 0.f, 0.f);
                    if (grow < M) {
                        v = *(const float4*)(Asrc + (size_t)grow * Ak + kp + lc4);
                        if (sc) { float s = rowscale[grow]; v.x *= s; v.y *= s; v.z *= s; v.w *= s; }
                    }
                    rv[j] = v;
                }
            }

            const uint32_t* aB = (const uint32_t*)sA;
#pragma unroll
            for (int ks = 0; ks < 4; ks++) {
                int kk = (p << 5) + ks * 8;
                uint2 bf[8];
                const uint2* wf = ((const uint2*)sW) + ((size_t)(kk >> 3) * 16 + (wn >> 3)) * 32 + lane;
#pragma unroll
                for (int j = 0; j < 8; j++) bf[j] = wf[j * 32];

#pragma unroll
                for (int mt = 0; mt < 2; mt++) {
                    int r = wm + mt * 16 + (lane >> 2);
                    int c = ks * 8 + (lane & 3);
                    uint32_t a0 = aB[r * AROW + c];
                    uint32_t a1 = aB[(r + 8) * AROW + c];
                    uint32_t a2 = aB[r * AROW + c + 4];
                    uint32_t a3 = aB[(r + 8) * AROW + c + 4];
#pragma unroll
                    for (int nt = 0; nt < 8; nt++)
                        mma_tf32(acc[mt][nt], a0, a1, a2, a3, bf[nt].x, bf[nt].y);
                }
            }
        }

        // epilogue: bias + relu, direct float2 stores (does not touch sA)
#pragma unroll
        for (int mt = 0; mt < 2; mt++) {
            int r0 = bm + wm + mt * 16 + (lane >> 2);
#pragma unroll
            for (int nt = 0; nt < 8; nt++) {
                int col = wn + nt * 8 + (lane & 3) * 2;
                float b0 = sB[col], b1 = sB[col + 1];
                float v0 = acc[mt][nt][0] + b0;
                float v1 = acc[mt][nt][1] + b1;
                float v2 = acc[mt][nt][2] + b0;
                float v3 = acc[mt][nt][3] + b1;
                if (act) {
                    v0 = fmaxf(v0, 0.f); v1 = fmaxf(v1, 0.f);
                    v2 = fmaxf(v2, 0.f); v3 = fmaxf(v3, 0.f);
                }
                if (r0 < M)     *(float2*)(C + (size_t)r0 * 128 + col)       = make_float2(v0, v1);
                if (r0 + 8 < M) *(float2*)(C + (size_t)(r0 + 8) * 128 + col) = make_float2(v2, v3);
            }
        }
    }
}

// -------- dist path layer0: y0 = relu(e[N,5] @ W0[5,128] + b0) --------
__global__ void dist0_kernel(const float* __restrict__ e, const float* __restrict__ W0,
                             const float* __restrict__ b0, float* __restrict__ out, int n) {
    __shared__ float sW[5 * 128];
    __shared__ float sb[128];
    int t = threadIdx.x;  // 128
    for (int i = t; i < 5 * 128; i += 128) sW[i] = W0[i];
    sb[t] = b0[t];
    __syncthreads();
    for (long long nd = blockIdx.x; nd < n; nd += gridDim.x) {
        const float* ev = e + nd * 5;
        float v = sb[t];
        v += ev[0] * sW[0 * 128 + t];
        v += ev[1] * sW[1 * 128 + t];
        v += ev[2] * sW[2 * 128 + t];
        v += ev[3] * sW[3 * 128 + t];
        v += ev[4] * sW[4 * 128 + t];
        out[nd * 128 + t] = fmaxf(v, 0.f);
    }
}

// -------- final: out[n] = sigmoid(feat.fW[0:128] + dist.fW[128:256] + fb) --------
__global__ void final_kernel(const float* __restrict__ feat, const float* __restrict__ dist,
                             const float* __restrict__ fW, const float* __restrict__ fb,
                             float* __restrict__ out, int n) {
    long long wg = (long long)blockIdx.x * 8 + (threadIdx.x >> 5);
    int lane = threadIdx.x & 31;
    if (wg >= n) return;
    float4 f = *(const float4*)(feat + wg * 128 + lane * 4);
    float4 w1 = *(const float4*)(fW + lane * 4);
    float4 d = *(const float4*)(dist + wg * 128 + lane * 4);
    float4 w2 = *(const float4*)(fW + 128 + lane * 4);
    float s = f.x * w1.x + f.y * w1.y + f.z * w1.z + f.w * w1.w
            + d.x * w2.x + d.y * w2.y + d.z * w2.z + d.w * w2.w;
#pragma unroll
    for (int off = 16; off; off >>= 1) s += __shfl_xor_sync(0xFFFFFFFFu, s, off);
    if (lane == 0) {
        float z = s + fb[0];
        out[wg] = 1.0f / (1.0f + expf(-z));
    }
}

extern "C" void kernel_launch(void* const* d_in, const int* in_sizes, int n_in,
                              void* d_out, int out_size) {
    const float* x          = (const float*)d_in[0];
    const void*  ei         = d_in[1];
    const float* eattr      = (const float*)d_in[2];
    const float* pre_W      = (const float*)d_in[3];
    const float* pre_b      = (const float*)d_in[4];
    const float* c1_Ws      = (const float*)d_in[5];
    const float* c1_Wn      = (const float*)d_in[6];
    const float* c1_b       = (const float*)d_in[7];
    const float* c2_Ws      = (const float*)d_in[8];
    const float* c2_Wn      = (const float*)d_in[9];
    const float* c2_b       = (const float*)d_in[10];
    const float* nodepost_W = (const float*)d_in[11];
    const float* nodepost_b = (const float*)d_in[12];
    const float* d_W0       = (const float*)d_in[13];
    const float* d_b0       = (const float*)d_in[14];
    const float* d_W1       = (const float*)d_in[15];
    const float* d_b1       = (const float*)d_in[16];
    const float* d_W2       = (const float*)d_in[17];
    const float* d_b2       = (const float*)d_in[18];
    const float* d_W3       = (const float*)d_in[19];
    const float* d_b3       = (const float*)d_in[20];
    const float* final_W    = (const float*)d_in[21];
    const float* final_b    = (const float*)d_in[22];
    float* out = (float*)d_out;

    int n = in_sizes[0] / FIN;
    long long E = (long long)in_sizes[1] / 2;

    float *bufA, *bufB, *bufC, *deg, *wbuf;
    cudaGetSymbolAddress((void**)&bufA, g_bufA);
    cudaGetSymbolAddress((void**)&bufB, g_bufB);
    cudaGetSymbolAddress((void**)&bufC, g_bufC);
    cudaGetSymbolAddress((void**)&deg, g_deg);
    cudaGetSymbolAddress((void**)&wbuf, g_wbuf);

    // fragment buffer layout
    float* f_pre  = wbuf;                  // 256x128 -> 32768
    float* f_c1s  = wbuf + 32768;
    float* f_c1n  = f_c1s + 16384;
    float* f_c2s  = f_c1n + 16384;
    float* f_c2n  = f_c2s + 16384;
    float* f_np   = f_c2n + 16384;
    float* f_d1   = f_np + 16384;
    float* f_d2   = f_d1 + 16384;
    float* f_d3   = f_d2 + 16384;

    const int SMEM_K256 = (256 * 128 + ABUF + 128) * 4;  // ~147 KB
    const int SMEM_K128 = (128 * 128 + ABUF + 128) * 4;  // ~84 KB
    cudaFuncSetAttribute(tc_gemm, cudaFuncAttributeMaxDynamicSharedMemorySize, SMEM_K256);

    const int nSM = 148;   // B200 (sm_100a); persistence via grid-stride is
                           // correct for any actual SM count
    int nMB = (n + 127) / 128;
    int gemm_grid = nSM < nMB ? nSM : nMB;

    long long nh4 = ((long long)n * H) / 4;
    int scat_grid = (int)((E + 7) / 8);

    detect_idx64_kernel<<<1, 1024>>>((const unsigned int*)ei);

    // weight fragment prep
    prepW_kernel<<<(16384 + 255) / 256, 256>>>(pre_W, f_pre, 256);
    prepW_kernel<<<(8192 + 255) / 256, 256>>>(c1_Ws, f_c1s, 128);
    prepW_kernel<<<(8192 + 255) / 256, 256>>>(c1_Wn, f_c1n, 128);
    prepW_kernel<<<(8192 + 255) / 256, 256>>>(c2_Ws, f_c2s, 128);
    prepW_kernel<<<(8192 + 255) / 256, 256>>>(c2_Wn, f_c2n, 128);
    prepW_kernel<<<(8192 + 255) / 256, 256>>>(nodepost_W, f_np, 128);
    prepW_kernel<<<(8192 + 255) / 256, 256>>>(d_W1, f_d1, 128);
    prepW_kernel<<<(8192 + 255) / 256, 256>>>(d_W2, f_d2, 128);
    prepW_kernel<<<(8192 + 255) / 256, 256>>>(d_W3, f_d3, 128);

    zero_kernel<<<(int)((n / 4 + 255) / 256) + 1, 256>>>(deg, (n + 3) / 4);
    deg_kernel<<<(int)((E + 255) / 256), 256>>>(ei, E);
    deginv_kernel<<<(n + 255) / 256, 256>>>(n);

    // pre: h0 = x @ pre_W + pre_b  -> bufA
    tc_gemm<<<gemm_grid, 256, SMEM_K256>>>(x, FIN, f_pre, nullptr, 0, nullptr, nullptr,
                                           pre_b, bufA, n, 0);

    // agg1 = scatter(h0) -> bufB
    zero_kernel<<<(int)((nh4 + 255) / 256), 256>>>(bufB, nh4);
    scatter_kernel<<<scat_grid, 256>>>(bufA, bufB, ei, E);

    // h1 = relu(h0@c1_Ws + deginv*agg1@c1_Wn + b) -> bufC
    tc_gemm<<<gemm_grid, 256, SMEM_K256>>>(bufA, H, f_c1s, bufB, H, f_c1n, deg,
                                           c1_b, bufC, n, 1);

    // agg2 = scatter(h1) -> bufB
    zero_kernel<<<(int)((nh4 + 255) / 256), 256>>>(bufB, nh4);
    scatter_kernel<<<scat_grid, 256>>>(bufC, bufB, ei, E);

    // h2 = relu(h1@c2_Ws + deginv*agg2@c2_Wn + b) -> bufA
    tc_gemm<<<gemm_grid, 256, SMEM_K256>>>(bufC, H, f_c2s, bufB, H, f_c2n, deg,
                                           c2_b, bufA, n, 1);

    // feat = h2 @ nodepost_W + b -> bufC
    tc_gemm<<<gemm_grid, 256, SMEM_K128>>>(bufA, H, f_np, nullptr, 0, nullptr, nullptr,
                                           nodepost_b, bufC, n, 0);

    // dist path: y0 -> bufB, then 3 GEMMs ping-pong
    dist0_kernel<<<2048, 128>>>(eattr, d_W0, d_b0, bufB, n);
    tc_gemm<<<gemm_grid, 256, SMEM_K128>>>(bufB, H, f_d1, nullptr, 0, nullptr, nullptr,
                                           d_b1, bufA, n, 1);
    tc_gemm<<<gemm_grid, 256, SMEM_K128>>>(bufA, H, f_d2, nullptr, 0, nullptr, nullptr,
                                           d_b2, bufB, n, 1);
    tc_gemm<<<gemm_grid, 256, SMEM_K128>>>(bufB, H, f_d3, nullptr, 0, nullptr, nullptr,
                                           d_b3, bufA, n, 0);

    final_kernel<<<(n + 7) / 8, 256>>>(bufC, bufA, final_W, final_b, out, n);
}

// round 9
// speedup vs baseline: 1.7227x; 1.0740x over previous
#include <cuda_runtime.h>
#include <cuda_bf16.h>
#include <math.h>
#include <cstdint>

// Problem constants (fixed shapes for this problem)
#define NMAX 100000
#define H 128
#define FIN 256

// -------- scratch (no allocation allowed) --------
__device__ float g_bufA[(size_t)NMAX * H];
__device__ float g_bufB[(size_t)NMAX * H];
__device__ float g_bufC[(size_t)NMAX * H];
__device__ float g_deg[NMAX];
__device__ float g_wbuf[32768 + 8 * 16384];          // tf32 weight fragments
__device__ __nv_bfloat16 g_hb16[(size_t)NMAX * H];   // bf16 copy of conv input h
__device__ __nv_bfloat16 g_aggb16[(size_t)NMAX * H]; // bf16 aggregation buffer
__device__ int   g_is64;

// ================ edge-index dtype detection ================
__global__ void detect_idx64_kernel(const unsigned int* __restrict__ ei) {
    int any = __syncthreads_or(ei[2 * threadIdx.x + 1] != 0u);
    if (threadIdx.x == 0) g_is64 = any ? 0 : 1;
}
__device__ __forceinline__ long long load_idx(const void* ei, long long i, int is64) {
    if (is64) return ((const long long*)ei)[i];
    return (long long)(((const int*)ei)[i]);
}

// ================ small kernels ================
__global__ void zero_kernel(float* __restrict__ p, long long n4) {
    long long i = (long long)blockIdx.x * blockDim.x + threadIdx.x;
    if (i < n4) ((float4*)p)[i] = make_float4(0.f, 0.f, 0.f, 0.f);
}
__global__ void deg_kernel(const void* __restrict__ ei, long long E) {
    long long e = (long long)blockIdx.x * blockDim.x + threadIdx.x;
    if (e >= E) return;
    int is64 = g_is64;
    long long dst = load_idx(ei, E + e, is64);
    atomicAdd(&g_deg[dst], 1.0f);
}
__global__ void deginv_kernel(int n) {
    int i = blockIdx.x * blockDim.x + threadIdx.x;
    if (i < n) g_deg[i] = 1.0f / fmaxf(g_deg[i], 1.0f);
}

// bf16 scatter-add: agg[dst] += h[src]; warp per edge; 8B per lane; vector RED
__global__ void scatter_b16_kernel(const __nv_bfloat16* __restrict__ h,
                                   __nv_bfloat16* __restrict__ agg,
                                   const void* __restrict__ ei, long long E) {
    long long w = (long long)blockIdx.x * 8 + (threadIdx.x >> 5);
    int lane = threadIdx.x & 31;
    if (w >= E) return;
    int is64 = g_is64;
    long long src = load_idx(ei, w, is64);
    long long dst = load_idx(ei, E + w, is64);
    uint2 v = ((const uint2*)(h + src * H))[lane];           // 4 bf16
    __nv_bfloat16* p = agg + dst * H + lane * 4;
    asm volatile("red.global.add.noftz.v2.bf16x2 [%0], {%1, %2};"
                 :: "l"(p), "r"(v.x), "r"(v.y) : "memory");
}

// ================ tf32 helpers ================
__device__ __forceinline__ uint32_t to_tf32(float f) {
    uint32_t r;
    asm("cvt.rna.tf32.f32 %0, %1;" : "=r"(r) : "f"(f));
    return r;
}
__device__ __forceinline__ void mma_tf32(float* c, uint32_t a0, uint32_t a1,
                                         uint32_t a2, uint32_t a3,
                                         uint32_t b0, uint32_t b1) {
    asm volatile(
        "mma.sync.aligned.m16n8k8.row.col.f32.tf32.tf32.f32 "
        "{%0,%1,%2,%3}, {%4,%5,%6,%7}, {%8,%9}, {%0,%1,%2,%3};"
        : "+f"(c[0]), "+f"(c[1]), "+f"(c[2]), "+f"(c[3])
        : "r"(a0), "r"(a1), "r"(a2), "r"(a3), "r"(b0), "r"(b1));
}
__device__ __forceinline__ uint32_t pack_bf16x2(float lo, float hi) {
    uint32_t r;
    asm("cvt.rn.bf16x2.f32 %0, %1, %2;" : "=r"(r) : "f"(hi), "f"(lo));
    return r;
}

// ================ fused weight fragment preparation (one launch) ================
// float2 out[kstep][ntile][lane]:
//   b0 = W[kstep*8 + (lane&3)]    [ntile*8 + (lane>>2)]
//   b1 = W[kstep*8 + (lane&3) + 4][ntile*8 + (lane>>2)], tf32-rounded.
__global__ void prepW_all(const float* W0, const float* W1, const float* W2,
                          const float* W3, const float* W4, const float* W5,
                          const float* W6, const float* W7, const float* W8,
                          float* __restrict__ wbuf) {
    int wid = blockIdx.y;
    const float* W; float* dst; int K;
    switch (wid) {
        case 0: W = W0; dst = wbuf;                 K = 256; break;
        case 1: W = W1; dst = wbuf + 32768;         K = 128; break;
        case 2: W = W2; dst = wbuf + 32768 + 16384; K = 128; break;
        case 3: W = W3; dst = wbuf + 32768 + 2 * 16384; K = 128; break;
        case 4: W = W4; dst = wbuf + 32768 + 3 * 16384; K = 128; break;
        case 5: W = W5; dst = wbuf + 32768 + 4 * 16384; K = 128; break;
        case 6: W = W6; dst = wbuf + 32768 + 5 * 16384; K = 128; break;
        case 7: W = W7; dst = wbuf + 32768 + 6 * 16384; K = 128; break;
        default: W = W8; dst = wbuf + 32768 + 7 * 16384; K = 128; break;
    }
    int idx = blockIdx.x * blockDim.x + threadIdx.x;
    int total = (K >> 3) * 16 * 32;
    if (idx >= total) return;
    int lane = idx & 31;
    int ntile = (idx >> 5) & 15;
    int kstep = idx >> 9;
    int k0 = kstep * 8 + (lane & 3);
    int nn = ntile * 8 + (lane >> 2);
    uint32_t b0 = to_tf32(W[k0 * 128 + nn]);
    uint32_t b1 = to_tf32(W[(k0 + 4) * 128 + nn]);
    ((uint2*)dst)[idx] = make_uint2(b0, b1);
}

// ================ persistent tensor-core GEMM (register double-buffered) ================
// C[M,128] = act( A1[M,K1]@W1 + (rowscale ⊙ A2b16[M,K2])@W2 + bias )
// A1 fp32; A2 (if present) is BF16 (the aggregation buffer).
// Optional dual-store of output as bf16 into Cb16 (feeds next scatter).
// Persistent CTAs; A panel = 128 rows x 32 k; full-coverage register prefetch.
#define AROW 36
#define ABUF (128 * AROW)

__global__ void __launch_bounds__(256)
tc_gemm(const float* __restrict__ A1, int K1, const float* __restrict__ Wf1,
        const __nv_bfloat16* __restrict__ A2, int K2, const float* __restrict__ Wf2,
        const float* __restrict__ rowscale, const float* __restrict__ bias,
        float* __restrict__ C, __nv_bfloat16* __restrict__ Cb16,
        int M, int act) {
    extern __shared__ float smem[];
    int KT = K1 + K2;
    float* sW = smem;                         // KT*128 floats (fragment order)
    float* sA = smem + (size_t)KT * 128;      // ABUF floats
    float* sB = sA + ABUF;                    // 128 floats bias

    int t = threadIdx.x, warp = t >> 5, lane = t & 31;
    int wm = (warp & 3) * 32;   // warp row offset
    int wn = (warp >> 2) * 64;  // warp col offset
    bool haveScale = (rowscale != nullptr);

    // one-time: weight fragments + bias to SMEM
    {
        const float4* s1 = (const float4*)Wf1;
        float4* d = (float4*)sW;
        for (int i = t; i < K1 * 32; i += 256) d[i] = s1[i];
        if (K2 > 0) {
            const float4* s2 = (const float4*)Wf2;
            float4* d2 = (float4*)(sW + (size_t)K1 * 128);
            for (int i = t; i < K2 * 32; i += 256) d2[i] = s2[i];
        }
        if (t < 128) sB[t] = bias[t];
    }
    __syncthreads();

    int nMB = (M + 127) >> 7;
    int nP = KT >> 5;

    // panel-load mapping: 1024 chunks of 4 values, 4 per thread (FULL 128x32 panel)
    int lrow = t >> 3;         // 0..31, actual rows lrow + j*32
    int lc4 = (t & 7) * 4;     // element offset 0..28 within 32-wide panel

    for (int mb = blockIdx.x; mb < nMB; mb += gridDim.x) {
        int bm = mb << 7;

        float acc[2][8][4];
#pragma unroll
        for (int a = 0; a < 2; a++)
#pragma unroll
            for (int b = 0; b < 8; b++)
#pragma unroll
                for (int c = 0; c < 4; c++) acc[a][b][c] = 0.f;

        // prefetch panel 0 into registers
        float4 rv[4];
#pragma unroll
        for (int j = 0; j < 4; j++) {
            int row = lrow + j * 32;
            int grow = bm + row;
            float4 v = make_float4(0.f, 0.f, 0.f, 0.f);
            if (grow < M) {
                if (K1 > 0) {
                    v = *(const float4*)(A1 + (size_t)grow * K1 + lc4);
                } else {
                    uint2 u = *(const uint2*)(A2 + (size_t)grow * K2 + lc4);
                    float2 p0 = __bfloat1622float2(*(__nv_bfloat162*)&u.x);
                    float2 p1 = __bfloat1622float2(*(__nv_bfloat162*)&u.y);
                    float s = haveScale ? rowscale[grow] : 1.0f;
                    v = make_float4(p0.x * s, p0.y * s, p1.x * s, p1.y * s);
                }
            }
            rv[j] = v;
        }

        for (int p = 0; p < nP; p++) {
            __syncthreads();   // previous panel's mma done -> sA free
#pragma unroll
            for (int j = 0; j < 4; j++) {
                int row = lrow + j * 32;
                uint32_t* st = (uint32_t*)(sA + row * AROW + lc4);
                st[0] = to_tf32(rv[j].x); st[1] = to_tf32(rv[j].y);
                st[2] = to_tf32(rv[j].z); st[3] = to_tf32(rv[j].w);
            }
            __syncthreads();   // panel visible

            // prefetch next panel into registers (latency hidden by mma below)
            if (p + 1 < nP) {
                int kt = (p + 1) << 5;
#pragma unroll
                for (int j = 0; j < 4; j++) {
                    int row = lrow + j * 32;
                    int grow = bm + row;
                    float4 v = make_float4(0.f, 0.f, 0.f, 0.f);
                    if (grow < M) {
                        if (kt < K1) {
                            v = *(const float4*)(A1 + (size_t)grow * K1 + kt + lc4);
                        } else {
                            int kp = kt - K1;
                            uint2 u = *(const uint2*)(A2 + (size_t)grow * K2 + kp + lc4);
                            float2 p0 = __bfloat1622float2(*(__nv_bfloat162*)&u.x);
                            float2 p1 = __bfloat1622float2(*(__nv_bfloat162*)&u.y);
                            float s = haveScale ? rowscale[grow] : 1.0f;
                            v = make_float4(p0.x * s, p0.y * s, p1.x * s, p1.y * s);
                        }
                    }
                    rv[j] = v;
                }
            }

            const uint32_t* aB = (const uint32_t*)sA;
#pragma unroll
            for (int ks = 0; ks < 4; ks++) {
                int kk = (p << 5) + ks * 8;
                uint2 bf[8];
                const uint2* wf = ((const uint2*)sW) + ((size_t)(kk >> 3) * 16 + (wn >> 3)) * 32 + lane;
#pragma unroll
                for (int j = 0; j < 8; j++) bf[j] = wf[j * 32];

#pragma unroll
                for (int mt = 0; mt < 2; mt++) {
                    int r = wm + mt * 16 + (lane >> 2);
                    int c = ks * 8 + (lane & 3);
                    uint32_t a0 = aB[r * AROW + c];
                    uint32_t a1 = aB[(r + 8) * AROW + c];
                    uint32_t a2 = aB[r * AROW + c + 4];
                    uint32_t a3 = aB[(r + 8) * AROW + c + 4];
#pragma unroll
                    for (int nt = 0; nt < 8; nt++)
                        mma_tf32(acc[mt][nt], a0, a1, a2, a3, bf[nt].x, bf[nt].y);
                }
            }
        }

        // epilogue: bias + relu; fp32 stores + optional bf16 dual store
#pragma unroll
        for (int mt = 0; mt < 2; mt++) {
            int r0 = bm + wm + mt * 16 + (lane >> 2);
#pragma unroll
            for (int nt = 0; nt < 8; nt++) {
                int col = wn + nt * 8 + (lane & 3) * 2;
                float b0 = sB[col], b1 = sB[col + 1];
                float v0 = acc[mt][nt][0] + b0;
                float v1 = acc[mt][nt][1] + b1;
                float v2 = acc[mt][nt][2] + b0;
                float v3 = acc[mt][nt][3] + b1;
                if (act) {
                    v0 = fmaxf(v0, 0.f); v1 = fmaxf(v1, 0.f);
                    v2 = fmaxf(v2, 0.f); v3 = fmaxf(v3, 0.f);
                }
                if (r0 < M) {
                    *(float2*)(C + (size_t)r0 * 128 + col) = make_float2(v0, v1);
                    if (Cb16) *(uint32_t*)(Cb16 + (size_t)r0 * 128 + col) = pack_bf16x2(v0, v1);
                }
                if (r0 + 8 < M) {
                    *(float2*)(C + (size_t)(r0 + 8) * 128 + col) = make_float2(v2, v3);
                    if (Cb16) *(uint32_t*)(Cb16 + (size_t)(r0 + 8) * 128 + col) = pack_bf16x2(v2, v3);
                }
            }
        }
    }
}

// -------- dist path layer0: y0 = relu(e[N,5] @ W0[5,128] + b0) --------
__global__ void dist0_kernel(const float* __restrict__ e, const float* __restrict__ W0,
                             const float* __restrict__ b0, float* __restrict__ out, int n) {
    __shared__ float sW[5 * 128];
    __shared__ float sb[128];
    int t = threadIdx.x;  // 128
    for (int i = t; i < 5 * 128; i += 128) sW[i] = W0[i];
    sb[t] = b0[t];
    __syncthreads();
    for (long long nd = blockIdx.x; nd < n; nd += gridDim.x) {
        const float* ev = e + nd * 5;
        float v = sb[t];
        v += ev[0] * sW[0 * 128 + t];
        v += ev[1] * sW[1 * 128 + t];
        v += ev[2] * sW[2 * 128 + t];
        v += ev[3] * sW[3 * 128 + t];
        v += ev[4] * sW[4 * 128 + t];
        out[nd * 128 + t] = fmaxf(v, 0.f);
    }
}

// -------- final: out[n] = sigmoid(feat.fW[0:128] + dist.fW[128:256] + fb) --------
__global__ void final_kernel(const float* __restrict__ feat, const float* __restrict__ dist,
                             const float* __restrict__ fW, const float* __restrict__ fb,
                             float* __restrict__ out, int n) {
    long long wg = (long long)blockIdx.x * 8 + (threadIdx.x >> 5);
    int lane = threadIdx.x & 31;
    if (wg >= n) return;
    float4 f = *(const float4*)(feat + wg * 128 + lane * 4);
    float4 w1 = *(const float4*)(fW + lane * 4);
    float4 d = *(const float4*)(dist + wg * 128 + lane * 4);
    float4 w2 = *(const float4*)(fW + 128 + lane * 4);
    float s = f.x * w1.x + f.y * w1.y + f.z * w1.z + f.w * w1.w
            + d.x * w2.x + d.y * w2.y + d.z * w2.z + d.w * w2.w;
#pragma unroll
    for (int off = 16; off; off >>= 1) s += __shfl_xor_sync(0xFFFFFFFFu, s, off);
    if (lane == 0) {
        float z = s + fb[0];
        out[wg] = 1.0f / (1.0f + expf(-z));
    }
}

extern "C" void kernel_launch(void* const* d_in, const int* in_sizes, int n_in,
                              void* d_out, int out_size) {
    const float* x          = (const float*)d_in[0];
    const void*  ei         = d_in[1];
    const float* eattr      = (const float*)d_in[2];
    const float* pre_W      = (const float*)d_in[3];
    const float* pre_b      = (const float*)d_in[4];
    const float* c1_Ws      = (const float*)d_in[5];
    const float* c1_Wn      = (const float*)d_in[6];
    const float* c1_b       = (const float*)d_in[7];
    const float* c2_Ws      = (const float*)d_in[8];
    const float* c2_Wn      = (const float*)d_in[9];
    const float* c2_b       = (const float*)d_in[10];
    const float* nodepost_W = (const float*)d_in[11];
    const float* nodepost_b = (const float*)d_in[12];
    const float* d_W0       = (const float*)d_in[13];
    const float* d_b0       = (const float*)d_in[14];
    const float* d_W1       = (const float*)d_in[15];
    const float* d_b1       = (const float*)d_in[16];
    const float* d_W2       = (const float*)d_in[17];
    const float* d_b2       = (const float*)d_in[18];
    const float* d_W3       = (const float*)d_in[19];
    const float* d_b3       = (const float*)d_in[20];
    const float* final_W    = (const float*)d_in[21];
    const float* final_b    = (const float*)d_in[22];
    float* out = (float*)d_out;

    int n = in_sizes[0] / FIN;
    long long E = (long long)in_sizes[1] / 2;

    float *bufA, *bufB, *bufC, *deg, *wbuf;
    __nv_bfloat16 *hb16, *aggb16;
    cudaGetSymbolAddress((void**)&bufA, g_bufA);
    cudaGetSymbolAddress((void**)&bufB, g_bufB);
    cudaGetSymbolAddress((void**)&bufC, g_bufC);
    cudaGetSymbolAddress((void**)&deg, g_deg);
    cudaGetSymbolAddress((void**)&wbuf, g_wbuf);
    cudaGetSymbolAddress((void**)&hb16, g_hb16);
    cudaGetSymbolAddress((void**)&aggb16, g_aggb16);

    // fragment buffer layout
    float* f_pre  = wbuf;                  // 256x128 -> 32768
    float* f_c1s  = wbuf + 32768;
    float* f_c1n  = f_c1s + 16384;
    float* f_c2s  = f_c1n + 16384;
    float* f_c2n  = f_c2s + 16384;
    float* f_np   = f_c2n + 16384;
    float* f_d1   = f_np + 16384;
    float* f_d2   = f_d1 + 16384;
    float* f_d3   = f_d2 + 16384;

    const int SMEM_K256 = (256 * 128 + ABUF + 128) * 4;  // ~147 KB
    const int SMEM_K128 = (128 * 128 + ABUF + 128) * 4;  // ~84 KB
    cudaFuncSetAttribute(tc_gemm, cudaFuncAttributeMaxDynamicSharedMemorySize, SMEM_K256);

    const int nSM = 148;   // B200 (sm_100a); grid-stride persistence is
                           // correct for any actual SM count
    int nMB = (n + 127) / 128;
    int gemm_grid = nSM < nMB ? nSM : nMB;

    long long aggz4 = (long long)n * 16;          // n*128 bf16 = n*16 float4
    int scat_grid = (int)((E + 7) / 8);

    detect_idx64_kernel<<<1, 1024>>>((const unsigned int*)ei);

    // weight fragment prep: ONE launch for all 9 weights
    {
        dim3 g(64, 9);
        prepW_all<<<g, 256>>>(pre_W, c1_Ws, c1_Wn, c2_Ws, c2_Wn,
                              nodepost_W, d_W1, d_W2, d_W3, wbuf);
    }

    zero_kernel<<<(int)((n / 4 + 255) / 256) + 1, 256>>>(deg, (n + 3) / 4);
    deg_kernel<<<(int)((E + 255) / 256), 256>>>(ei, E);
    deginv_kernel<<<(n + 255) / 256, 256>>>(n);

    // pre: h0 = x @ pre_W + pre_b  -> bufA (fp32) + hb16 (bf16)
    tc_gemm<<<gemm_grid, 256, SMEM_K256>>>(x, FIN, f_pre, nullptr, 0, nullptr, nullptr,
                                           pre_b, bufA, hb16, n, 0);

    // agg1 = scatter_b16(h0) -> aggb16
    zero_kernel<<<(int)((aggz4 + 255) / 256), 256>>>((float*)aggb16, aggz4);
    scatter_b16_kernel<<<scat_grid, 256>>>(hb16, aggb16, ei, E);

    // h1 = relu(h0@c1_Ws + deginv*agg1@c1_Wn + b) -> bufC (fp32) + hb16 (bf16)
    tc_gemm<<<gemm_grid, 256, SMEM_K256>>>(bufA, H, f_c1s, aggb16, H, f_c1n, deg,
                                           c1_b, bufC, hb16, n, 1);

    // agg2 = scatter_b16(h1) -> aggb16
    zero_kernel<<<(int)((aggz4 + 255) / 256), 256>>>((float*)aggb16, aggz4);
    scatter_b16_kernel<<<scat_grid, 256>>>(hb16, aggb16, ei, E);

    // h2 = relu(h1@c2_Ws + deginv*agg2@c2_Wn + b) -> bufA
    tc_gemm<<<gemm_grid, 256, SMEM_K256>>>(bufC, H, f_c2s, aggb16, H, f_c2n, deg,
                                           c2_b, bufA, nullptr, n, 1);

    // feat = h2 @ nodepost_W + b -> bufC
    tc_gemm<<<gemm_grid, 256, SMEM_K128>>>(bufA, H, f_np, nullptr, 0, nullptr, nullptr,
                                           nodepost_b, bufC, nullptr, n, 0);

    // dist path: y0 -> bufB, then 3 GEMMs ping-pong (fp32)
    dist0_kernel<<<2048, 128>>>(eattr, d_W0, d_b0, bufB, n);
    tc_gemm<<<gemm_grid, 256, SMEM_K128>>>(bufB, H, f_d1, nullptr, 0, nullptr, nullptr,
                                           d_b1, bufA, nullptr, n, 1);
    tc_gemm<<<gemm_grid, 256, SMEM_K128>>>(bufA, H, f_d2, nullptr, 0, nullptr, nullptr,
                                           d_b2, bufB, nullptr, n, 1);
    tc_gemm<<<gemm_grid, 256, SMEM_K128>>>(bufB, H, f_d3, nullptr, 0, nullptr, nullptr,
                                           d_b3, bufA, nullptr, n, 0);

    final_kernel<<<(n + 7) / 8, 256>>>(bufC, bufA, final_W, final_b, out, n);
}

// round 10
// speedup vs baseline: 2.0351x; 1.1813x over previous
#include <cuda_runtime.h>
#include <cuda_bf16.h>
#include <math.h>
#include <cstdint>

// Problem constants (fixed shapes for this problem)
#define NMAX 100000
#define H 128
#define FIN 256

// -------- scratch (no allocation allowed) --------
__device__ float g_bufA[(size_t)NMAX * H];
__device__ float g_bufB[(size_t)NMAX * H];
__device__ float g_bufC[(size_t)NMAX * H];
__device__ float g_deg[NMAX];
__device__ float g_wbuf[32768 + 8 * 16384];          // tf32 weight fragments
__device__ __nv_bfloat16 g_hb16[(size_t)NMAX * H];   // bf16 copy of conv input h
__device__ __nv_bfloat16 g_aggb16[(size_t)NMAX * H]; // bf16 aggregation buffer
__device__ int   g_is64;

// ================ edge-index dtype detection ================
__global__ void detect_idx64_kernel(const unsigned int* __restrict__ ei) {
    int any = __syncthreads_or(ei[2 * threadIdx.x + 1] != 0u);
    if (threadIdx.x == 0) g_is64 = any ? 0 : 1;
}
__device__ __forceinline__ long long load_idx(const void* ei, long long i, int is64) {
    if (is64) return ((const long long*)ei)[i];
    return (long long)(((const int*)ei)[i]);
}

// ================ small kernels ================
__global__ void zero_kernel(float* __restrict__ p, long long n4) {
    long long i = (long long)blockIdx.x * blockDim.x + threadIdx.x;
    if (i < n4) ((float4*)p)[i] = make_float4(0.f, 0.f, 0.f, 0.f);
}
__global__ void deg_kernel(const void* __restrict__ ei, long long E) {
    long long e = (long long)blockIdx.x * blockDim.x + threadIdx.x;
    if (e >= E) return;
    int is64 = g_is64;
    long long dst = load_idx(ei, E + e, is64);
    atomicAdd(&g_deg[dst], 1.0f);
}
__global__ void deginv_kernel(int n) {
    int i = blockIdx.x * blockDim.x + threadIdx.x;
    if (i < n) g_deg[i] = 1.0f / fmaxf(g_deg[i], 1.0f);
}

// bf16 scatter-add: agg[dst] += h[src].
// HALF-WARP per edge: 16 lanes x 16B (v4.bf16x2) -> halves RED lane-ops vs v2.
__global__ void scatter_b16_kernel(const __nv_bfloat16* __restrict__ h,
                                   __nv_bfloat16* __restrict__ agg,
                                   const void* __restrict__ ei, long long E) {
    long long e = (long long)blockIdx.x * 16 + (threadIdx.x >> 4);
    int lane = threadIdx.x & 15;
    if (e >= E) return;
    int is64 = g_is64;
    long long src = load_idx(ei, e, is64);
    long long dst = load_idx(ei, E + e, is64);
    uint4 v = ((const uint4*)(h + src * H))[lane];            // 8 bf16
    __nv_bfloat16* p = agg + dst * H + lane * 8;
    asm volatile("red.global.add.noftz.v4.bf16x2 [%0], {%1, %2, %3, %4};"
                 :: "l"(p), "r"(v.x), "r"(v.y), "r"(v.z), "r"(v.w) : "memory");
}

// ================ tf32 helpers ================
__device__ __forceinline__ uint32_t to_tf32(float f) {
    uint32_t r;
    asm("cvt.rna.tf32.f32 %0, %1;" : "=r"(r) : "f"(f));
    return r;
}
__device__ __forceinline__ void mma_tf32(float* c, uint32_t a0, uint32_t a1,
                                         uint32_t a2, uint32_t a3,
                                         uint32_t b0, uint32_t b1) {
    asm volatile(
        "mma.sync.aligned.m16n8k8.row.col.f32.tf32.tf32.f32 "
        "{%0,%1,%2,%3}, {%4,%5,%6,%7}, {%8,%9}, {%0,%1,%2,%3};"
        : "+f"(c[0]), "+f"(c[1]), "+f"(c[2]), "+f"(c[3])
        : "r"(a0), "r"(a1), "r"(a2), "r"(a3), "r"(b0), "r"(b1));
}
__device__ __forceinline__ uint32_t pack_bf16x2(float lo, float hi) {
    uint32_t r;
    asm("cvt.rn.bf16x2.f32 %0, %1, %2;" : "=r"(r) : "f"(hi), "f"(lo));
    return r;
}

// ================ fused weight fragment preparation (one launch) ================
__global__ void prepW_all(const float* W0, const float* W1, const float* W2,
                          const float* W3, const float* W4, const float* W5,
                          const float* W6, const float* W7, const float* W8,
                          float* __restrict__ wbuf) {
    int wid = blockIdx.y;
    const float* W; float* dst; int K;
    switch (wid) {
        case 0: W = W0; dst = wbuf;                 K = 256; break;
        case 1: W = W1; dst = wbuf + 32768;         K = 128; break;
        case 2: W = W2; dst = wbuf + 32768 + 16384; K = 128; break;
        case 3: W = W3; dst = wbuf + 32768 + 2 * 16384; K = 128; break;
        case 4: W = W4; dst = wbuf + 32768 + 3 * 16384; K = 128; break;
        case 5: W = W5; dst = wbuf + 32768 + 4 * 16384; K = 128; break;
        case 6: W = W6; dst = wbuf + 32768 + 5 * 16384; K = 128; break;
        case 7: W = W7; dst = wbuf + 32768 + 6 * 16384; K = 128; break;
        default: W = W8; dst = wbuf + 32768 + 7 * 16384; K = 128; break;
    }
    int idx = blockIdx.x * blockDim.x + threadIdx.x;
    int total = (K >> 3) * 16 * 32;
    if (idx >= total) return;
    int lane = idx & 31;
    int ntile = (idx >> 5) & 15;
    int kstep = idx >> 9;
    int k0 = kstep * 8 + (lane & 3);
    int nn = ntile * 8 + (lane >> 2);
    uint32_t b0 = to_tf32(W[k0 * 128 + nn]);
    uint32_t b1 = to_tf32(W[(k0 + 4) * 128 + nn]);
    ((uint2*)dst)[idx] = make_uint2(b0, b1);
}

// ================ persistent tensor-core GEMM (register double-buffered) ================
// C[M,128] = act( A1[M,K1]@W1 + (rowscale ⊙ A2b16[M,K2])@W2 + bias )
// A1 fp32; A2 (if present) is BF16 (the aggregation buffer).
// Optional dual-store of output as bf16 into Cb16 (feeds next scatter).
#define AROW 36
#define ABUF (128 * AROW)

__global__ void __launch_bounds__(256)
tc_gemm(const float* __restrict__ A1, int K1, const float* __restrict__ Wf1,
        const __nv_bfloat16* __restrict__ A2, int K2, const float* __restrict__ Wf2,
        const float* __restrict__ rowscale, const float* __restrict__ bias,
        float* __restrict__ C, __nv_bfloat16* __restrict__ Cb16,
        int M, int act) {
    extern __shared__ float smem[];
    int KT = K1 + K2;
    float* sW = smem;                         // KT*128 floats (fragment order)
    float* sA = smem + (size_t)KT * 128;      // ABUF floats
    float* sB = sA + ABUF;                    // 128 floats bias

    int t = threadIdx.x, warp = t >> 5, lane = t & 31;
    int wm = (warp & 3) * 32;   // warp row offset
    int wn = (warp >> 2) * 64;  // warp col offset
    bool haveScale = (rowscale != nullptr);

    // one-time: weight fragments + bias to SMEM
    {
        const float4* s1 = (const float4*)Wf1;
        float4* d = (float4*)sW;
        for (int i = t; i < K1 * 32; i += 256) d[i] = s1[i];
        if (K2 > 0) {
            const float4* s2 = (const float4*)Wf2;
            float4* d2 = (float4*)(sW + (size_t)K1 * 128);
            for (int i = t; i < K2 * 32; i += 256) d2[i] = s2[i];
        }
        if (t < 128) sB[t] = bias[t];
    }
    __syncthreads();

    int nMB = (M + 127) >> 7;
    int nP = KT >> 5;

    // panel-load mapping: 1024 chunks of 4 values, 4 per thread (FULL 128x32 panel)
    int lrow = t >> 3;         // 0..31, actual rows lrow + j*32
    int lc4 = (t & 7) * 4;     // element offset 0..28 within 32-wide panel

    for (int mb = blockIdx.x; mb < nMB; mb += gridDim.x) {
        int bm = mb << 7;

        float acc[2][8][4];
#pragma unroll
        for (int a = 0; a < 2; a++)
#pragma unroll
            for (int b = 0; b < 8; b++)
#pragma unroll
                for (int c = 0; c < 4; c++) acc[a][b][c] = 0.f;

        // prefetch panel 0 into registers
        float4 rv[4];
#pragma unroll
        for (int j = 0; j < 4; j++) {
            int row = lrow + j * 32;
            int grow = bm + row;
            float4 v = make_float4(0.f, 0.f, 0.f, 0.f);
            if (grow < M) {
                if (K1 > 0) {
                    v = *(const float4*)(A1 + (size_t)grow * K1 + lc4);
                } else {
                    uint2 u = *(const uint2*)(A2 + (size_t)grow * K2 + lc4);
                    float2 p0 = __bfloat1622float2(*(__nv_bfloat162*)&u.x);
                    float2 p1 = __bfloat1622float2(*(__nv_bfloat162*)&u.y);
                    float s = haveScale ? rowscale[grow] : 1.0f;
                    v = make_float4(p0.x * s, p0.y * s, p1.x * s, p1.y * s);
                }
            }
            rv[j] = v;
        }

        for (int p = 0; p < nP; p++) {
            __syncthreads();   // previous panel's mma done -> sA free
#pragma unroll
            for (int j = 0; j < 4; j++) {
                int row = lrow + j * 32;
                uint32_t* st = (uint32_t*)(sA + row * AROW + lc4);
                st[0] = to_tf32(rv[j].x); st[1] = to_tf32(rv[j].y);
                st[2] = to_tf32(rv[j].z); st[3] = to_tf32(rv[j].w);
            }
            __syncthreads();   // panel visible

            // prefetch next panel into registers (latency hidden by mma below)
            if (p + 1 < nP) {
                int kt = (p + 1) << 5;
#pragma unroll
                for (int j = 0; j < 4; j++) {
                    int row = lrow + j * 32;
                    int grow = bm + row;
                    float4 v = make_float4(0.f, 0.f, 0.f, 0.f);
                    if (grow < M) {
                        if (kt < K1) {
                            v = *(const float4*)(A1 + (size_t)grow * K1 + kt + lc4);
                        } else {
                            int kp = kt - K1;
                            uint2 u = *(const uint2*)(A2 + (size_t)grow * K2 + kp + lc4);
                            float2 p0 = __bfloat1622float2(*(__nv_bfloat162*)&u.x);
                            float2 p1 = __bfloat1622float2(*(__nv_bfloat162*)&u.y);
                            float s = haveScale ? rowscale[grow] : 1.0f;
                            v = make_float4(p0.x * s, p0.y * s, p1.x * s, p1.y * s);
                        }
                    }
                    rv[j] = v;
                }
            }

            const uint32_t* aB = (const uint32_t*)sA;
#pragma unroll
            for (int ks = 0; ks < 4; ks++) {
                int kk = (p << 5) + ks * 8;
                uint2 bf[8];
                const uint2* wf = ((const uint2*)sW) + ((size_t)(kk >> 3) * 16 + (wn >> 3)) * 32 + lane;
#pragma unroll
                for (int j = 0; j < 8; j++) bf[j] = wf[j * 32];

#pragma unroll
                for (int mt = 0; mt < 2; mt++) {
                    int r = wm + mt * 16 + (lane >> 2);
                    int c = ks * 8 + (lane & 3);
                    uint32_t a0 = aB[r * AROW + c];
                    uint32_t a1 = aB[(r + 8) * AROW + c];
                    uint32_t a2 = aB[r * AROW + c + 4];
                    uint32_t a3 = aB[(r + 8) * AROW + c + 4];
#pragma unroll
                    for (int nt = 0; nt < 8; nt++)
                        mma_tf32(acc[mt][nt], a0, a1, a2, a3, bf[nt].x, bf[nt].y);
                }
            }
        }

        // epilogue: bias + relu; fp32 stores + optional bf16 dual store
#pragma unroll
        for (int mt = 0; mt < 2; mt++) {
            int r0 = bm + wm + mt * 16 + (lane >> 2);
#pragma unroll
            for (int nt = 0; nt < 8; nt++) {
                int col = wn + nt * 8 + (lane & 3) * 2;
                float b0 = sB[col], b1 = sB[col + 1];
                float v0 = acc[mt][nt][0] + b0;
                float v1 = acc[mt][nt][1] + b1;
                float v2 = acc[mt][nt][2] + b0;
                float v3 = acc[mt][nt][3] + b1;
                if (act) {
                    v0 = fmaxf(v0, 0.f); v1 = fmaxf(v1, 0.f);
                    v2 = fmaxf(v2, 0.f); v3 = fmaxf(v3, 0.f);
                }
                if (r0 < M) {
                    *(float2*)(C + (size_t)r0 * 128 + col) = make_float2(v0, v1);
                    if (Cb16) *(uint32_t*)(Cb16 + (size_t)r0 * 128 + col) = pack_bf16x2(v0, v1);
                }
                if (r0 + 8 < M) {
                    *(float2*)(C + (size_t)(r0 + 8) * 128 + col) = make_float2(v2, v3);
                    if (Cb16) *(uint32_t*)(Cb16 + (size_t)(r0 + 8) * 128 + col) = pack_bf16x2(v2, v3);
                }
            }
        }
    }
}

// -------- dist path layer0: y0 = relu(e[N,5] @ W0[5,128] + b0) --------
__global__ void dist0_kernel(const float* __restrict__ e, const float* __restrict__ W0,
                             const float* __restrict__ b0, float* __restrict__ out, int n) {
    __shared__ float sW[5 * 128];
    __shared__ float sb[128];
    int t = threadIdx.x;  // 128
    for (int i = t; i < 5 * 128; i += 128) sW[i] = W0[i];
    sb[t] = b0[t];
    __syncthreads();
    for (long long nd = blockIdx.x; nd < n; nd += gridDim.x) {
        const float* ev = e + nd * 5;
        float v = sb[t];
        v += ev[0] * sW[0 * 128 + t];
        v += ev[1] * sW[1 * 128 + t];
        v += ev[2] * sW[2 * 128 + t];
        v += ev[3] * sW[3 * 128 + t];
        v += ev[4] * sW[4 * 128 + t];
        out[nd * 128 + t] = fmaxf(v, 0.f);
    }
}

// -------- final: out[n] = sigmoid(feat.fW[0:128] + dist.fW[128:256] + fb) --------
__global__ void final_kernel(const float* __restrict__ feat, const float* __restrict__ dist,
                             const float* __restrict__ fW, const float* __restrict__ fb,
                             float* __restrict__ out, int n) {
    long long wg = (long long)blockIdx.x * 8 + (threadIdx.x >> 5);
    int lane = threadIdx.x & 31;
    if (wg >= n) return;
    float4 f = *(const float4*)(feat + wg * 128 + lane * 4);
    float4 w1 = *(const float4*)(fW + lane * 4);
    float4 d = *(const float4*)(dist + wg * 128 + lane * 4);
    float4 w2 = *(const float4*)(fW + 128 + lane * 4);
    float s = f.x * w1.x + f.y * w1.y + f.z * w1.z + f.w * w1.w
            + d.x * w2.x + d.y * w2.y + d.z * w2.z + d.w * w2.w;
#pragma unroll
    for (int off = 16; off; off >>= 1) s += __shfl_xor_sync(0xFFFFFFFFu, s, off);
    if (lane == 0) {
        float z = s + fb[0];
        out[wg] = 1.0f / (1.0f + expf(-z));
    }
}

extern "C" void kernel_launch(void* const* d_in, const int* in_sizes, int n_in,
                              void* d_out, int out_size) {
    const float* x          = (const float*)d_in[0];
    const void*  ei         = d_in[1];
    const float* eattr      = (const float*)d_in[2];
    const float* pre_W      = (const float*)d_in[3];
    const float* pre_b      = (const float*)d_in[4];
    const float* c1_Ws      = (const float*)d_in[5];
    const float* c1_Wn      = (const float*)d_in[6];
    const float* c1_b       = (const float*)d_in[7];
    const float* c2_Ws      = (const float*)d_in[8];
    const float* c2_Wn      = (const float*)d_in[9];
    const float* c2_b       = (const float*)d_in[10];
    const float* nodepost_W = (const float*)d_in[11];
    const float* nodepost_b = (const float*)d_in[12];
    const float* d_W0       = (const float*)d_in[13];
    const float* d_b0       = (const float*)d_in[14];
    const float* d_W1       = (const float*)d_in[15];
    const float* d_b1       = (const float*)d_in[16];
    const float* d_W2       = (const float*)d_in[17];
    const float* d_b2       = (const float*)d_in[18];
    const float* d_W3       = (const float*)d_in[19];
    const float* d_b3       = (const float*)d_in[20];
    const float* final_W    = (const float*)d_in[21];
    const float* final_b    = (const float*)d_in[22];
    float* out = (float*)d_out;

    int n = in_sizes[0] / FIN;
    long long E = (long long)in_sizes[1] / 2;

    float *bufA, *bufB, *bufC, *deg, *wbuf;
    __nv_bfloat16 *hb16, *aggb16;
    cudaGetSymbolAddress((void**)&bufA, g_bufA);
    cudaGetSymbolAddress((void**)&bufB, g_bufB);
    cudaGetSymbolAddress((void**)&bufC, g_bufC);
    cudaGetSymbolAddress((void**)&deg, g_deg);
    cudaGetSymbolAddress((void**)&wbuf, g_wbuf);
    cudaGetSymbolAddress((void**)&hb16, g_hb16);
    cudaGetSymbolAddress((void**)&aggb16, g_aggb16);

    // fragment buffer layout
    float* f_pre  = wbuf;                  // 256x128 -> 32768
    float* f_c1s  = wbuf + 32768;
    float* f_c1n  = f_c1s + 16384;
    float* f_c2s  = f_c1n + 16384;
    float* f_c2n  = f_c2s + 16384;
    float* f_np   = f_c2n + 16384;
    float* f_d1   = f_np + 16384;
    float* f_d2   = f_d1 + 16384;
    float* f_d3   = f_d2 + 16384;

    const int SMEM_K256 = (256 * 128 + ABUF + 128) * 4;  // ~147 KB
    const int SMEM_K128 = (128 * 128 + ABUF + 128) * 4;  // ~84 KB
    cudaFuncSetAttribute(tc_gemm, cudaFuncAttributeMaxDynamicSharedMemorySize, SMEM_K256);

    const int nSM = 148;   // B200 (sm_100a); grid-stride persistence is
                           // correct for any actual SM count
    int nMB = (n + 127) / 128;
    int gemm_grid = nSM < nMB ? nSM : nMB;
    int gemm_grid2 = (2 * nSM) < nMB ? (2 * nSM) : nMB;  // K=128: 2 CTAs/SM if regs allow

    long long aggz4 = (long long)n * 16;          // n*128 bf16 = n*16 float4
    int scat_grid = (int)((E + 15) / 16);         // 16 edges per 256-thread block

    detect_idx64_kernel<<<1, 1024>>>((const unsigned int*)ei);

    // weight fragment prep: ONE launch for all 9 weights
    {
        dim3 g(64, 9);
        prepW_all<<<g, 256>>>(pre_W, c1_Ws, c1_Wn, c2_Ws, c2_Wn,
                              nodepost_W, d_W1, d_W2, d_W3, wbuf);
    }

    zero_kernel<<<(int)((n / 4 + 255) / 256) + 1, 256>>>(deg, (n + 3) / 4);
    deg_kernel<<<(int)((E + 255) / 256), 256>>>(ei, E);
    deginv_kernel<<<(n + 255) / 256, 256>>>(n);

    // pre: h0 = x @ pre_W + pre_b  -> bufA (fp32) + hb16 (bf16)
    tc_gemm<<<gemm_grid, 256, SMEM_K256>>>(x, FIN, f_pre, nullptr, 0, nullptr, nullptr,
                                           pre_b, bufA, hb16, n, 0);

    // agg1 = scatter_b16(h0) -> aggb16
    zero_kernel<<<(int)((aggz4 + 255) / 256), 256>>>((float*)aggb16, aggz4);
    scatter_b16_kernel<<<scat_grid, 256>>>(hb16, aggb16, ei, E);

    // h1 = relu(h0@c1_Ws + deginv*agg1@c1_Wn + b) -> bufC (fp32) + hb16 (bf16)
    tc_gemm<<<gemm_grid, 256, SMEM_K256>>>(bufA, H, f_c1s, aggb16, H, f_c1n, deg,
                                           c1_b, bufC, hb16, n, 1);

    // agg2 = scatter_b16(h1) -> aggb16
    zero_kernel<<<(int)((aggz4 + 255) / 256), 256>>>((float*)aggb16, aggz4);
    scatter_b16_kernel<<<scat_grid, 256>>>(hb16, aggb16, ei, E);

    // h2 = relu(h1@c2_Ws + deginv*agg2@c2_Wn + b) -> bufA
    tc_gemm<<<gemm_grid, 256, SMEM_K256>>>(bufC, H, f_c2s, aggb16, H, f_c2n, deg,
                                           c2_b, bufA, nullptr, n, 1);

    // feat = h2 @ nodepost_W + b -> bufC
    tc_gemm<<<gemm_grid2, 256, SMEM_K128>>>(bufA, H, f_np, nullptr, 0, nullptr, nullptr,
                                            nodepost_b, bufC, nullptr, n, 0);

    // dist path: y0 -> bufB, then 3 GEMMs ping-pong (fp32)
    dist0_kernel<<<2048, 128>>>(eattr, d_W0, d_b0, bufB, n);
    tc_gemm<<<gemm_grid2, 256, SMEM_K128>>>(bufB, H, f_d1, nullptr, 0, nullptr, nullptr,
                                            d_b1, bufA, nullptr, n, 1);
    tc_gemm<<<gemm_grid2, 256, SMEM_K128>>>(bufA, H, f_d2, nullptr, 0, nullptr, nullptr,
                                            d_b2, bufB, nullptr, n, 1);
    tc_gemm<<<gemm_grid2, 256, SMEM_K128>>>(bufB, H, f_d3, nullptr, 0, nullptr, nullptr,
                                            d_b3, bufA, nullptr, n, 0);

    final_kernel<<<(n + 7) / 8, 256>>>(bufC, bufA, final_W, final_b, out, n);
}

// round 12
// speedup vs baseline: 2.3558x; 1.1575x over previous
#include <cuda_runtime.h>
#include <cuda_bf16.h>
#include <math.h>
#include <cstdint>

// Problem constants (fixed shapes for this problem)
#define NMAX 100000
#define H 128
#define FIN 256

// -------- scratch (no allocation allowed) --------
__device__ float g_bufA[(size_t)NMAX * H];
__device__ float g_bufB[(size_t)NMAX * H];
__device__ float g_bufC[(size_t)NMAX * H];
__device__ float g_deg[NMAX];
__device__ float g_wbuf[16384 + 8 * 8192];           // bf16 weight fragments
__device__ __nv_bfloat16 g_hb16[(size_t)NMAX * H];   // bf16 copy of conv input h
__device__ __nv_bfloat16 g_aggb16[(size_t)NMAX * H]; // bf16 aggregation buffer
__device__ int   g_is64;

// ================ edge-index dtype detection ================
__global__ void detect_idx64_kernel(const unsigned int* __restrict__ ei) {
    int any = __syncthreads_or(ei[2 * threadIdx.x + 1] != 0u);
    if (threadIdx.x == 0) g_is64 = any ? 0 : 1;
}
__device__ __forceinline__ long long load_idx(const void* ei, long long i, int is64) {
    if (is64) return ((const long long*)ei)[i];
    return (long long)(((const int*)ei)[i]);
}

// ================ small kernels ================
__global__ void zero_kernel(float* __restrict__ p, long long n4) {
    long long i = (long long)blockIdx.x * blockDim.x + threadIdx.x;
    if (i < n4) ((float4*)p)[i] = make_float4(0.f, 0.f, 0.f, 0.f);
}
__global__ void deg_kernel(const void* __restrict__ ei, long long E) {
    long long e = (long long)blockIdx.x * blockDim.x + threadIdx.x;
    if (e >= E) return;
    int is64 = g_is64;
    long long dst = load_idx(ei, E + e, is64);
    atomicAdd(&g_deg[dst], 1.0f);
}
__global__ void deginv_kernel(int n) {
    int i = blockIdx.x * blockDim.x + threadIdx.x;
    if (i < n) g_deg[i] = 1.0f / fmaxf(g_deg[i], 1.0f);
}

// bf16 scatter-add: agg[dst] += h[src].
// HALF-WARP per edge: 16 lanes x 16B (v4.bf16x2).
__global__ void scatter_b16_kernel(const __nv_bfloat16* __restrict__ h,
                                   __nv_bfloat16* __restrict__ agg,
                                   const void* __restrict__ ei, long long E) {
    long long e = (long long)blockIdx.x * 16 + (threadIdx.x >> 4);
    int lane = threadIdx.x & 15;
    if (e >= E) return;
    int is64 = g_is64;
    long long src = load_idx(ei, e, is64);
    long long dst = load_idx(ei, E + e, is64);
    uint4 v = ((const uint4*)(h + src * H))[lane];            // 8 bf16
    __nv_bfloat16* p = agg + dst * H + lane * 8;
    asm volatile("red.global.add.noftz.v4.bf16x2 [%0], {%1, %2, %3, %4};"
                 :: "l"(p), "r"(v.x), "r"(v.y), "r"(v.z), "r"(v.w) : "memory");
}

// ================ bf16 helpers ================
__device__ __forceinline__ uint32_t pack_bf16x2(float lo, float hi) {
    uint32_t r;
    asm("cvt.rn.bf16x2.f32 %0, %1, %2;" : "=r"(r) : "f"(hi), "f"(lo));
    return r;
}
__device__ __forceinline__ void mma_bf16(float* c, uint32_t a0, uint32_t a1,
                                         uint32_t a2, uint32_t a3,
                                         uint32_t b0, uint32_t b1) {
    asm volatile(
        "mma.sync.aligned.m16n8k16.row.col.f32.bf16.bf16.f32 "
        "{%0,%1,%2,%3}, {%4,%5,%6,%7}, {%8,%9}, {%0,%1,%2,%3};"
        : "+f"(c[0]), "+f"(c[1]), "+f"(c[2]), "+f"(c[3])
        : "r"(a0), "r"(a1), "r"(a2), "r"(a3), "r"(b0), "r"(b1));
}

// ================ fused weight fragment preparation (one launch) ================
// m16n8k16 bf16 B-fragment order, uint2 out[kstep16][ntile][lane]:
//   b0 = {W[k0][n], W[k0+1][n]},  b1 = {W[k0+8][n], W[k0+9][n]}
//   with k0 = kstep*16 + (lane&3)*2,  n = ntile*8 + (lane>>2).
__global__ void prepW_all(const float* W0, const float* W1, const float* W2,
                          const float* W3, const float* W4, const float* W5,
                          const float* W6, const float* W7, const float* W8,
                          float* __restrict__ wbuf) {
    int wid = blockIdx.y;
    const float* W; float* dst; int K;
    switch (wid) {
        case 0: W = W0; dst = wbuf;                K = 256; break;
        case 1: W = W1; dst = wbuf + 16384;        K = 128; break;
        case 2: W = W2; dst = wbuf + 16384 + 8192; K = 128; break;
        case 3: W = W3; dst = wbuf + 16384 + 2 * 8192; K = 128; break;
        case 4: W = W4; dst = wbuf + 16384 + 3 * 8192; K = 128; break;
        case 5: W = W5; dst = wbuf + 16384 + 4 * 8192; K = 128; break;
        case 6: W = W6; dst = wbuf + 16384 + 5 * 8192; K = 128; break;
        case 7: W = W7; dst = wbuf + 16384 + 6 * 8192; K = 128; break;
        default: W = W8; dst = wbuf + 16384 + 7 * 8192; K = 128; break;
    }
    int idx = blockIdx.x * blockDim.x + threadIdx.x;
    int total = (K >> 4) * 16 * 32;
    if (idx >= total) return;
    int lane = idx & 31;
    int ntile = (idx >> 5) & 15;
    int kstep = idx >> 9;
    int k0 = kstep * 16 + (lane & 3) * 2;
    int nn = ntile * 8 + (lane >> 2);
    uint32_t b0 = pack_bf16x2(W[k0 * 128 + nn], W[(k0 + 1) * 128 + nn]);
    uint32_t b1 = pack_bf16x2(W[(k0 + 8) * 128 + nn], W[(k0 + 9) * 128 + nn]);
    ((uint2*)dst)[idx] = make_uint2(b0, b1);
}

// ================ persistent tensor-core GEMM (bf16 m16n8k16) ================
// C[M,128] = act( A1[M,K1]@W1 + (rowscale ⊙ A2b16[M,K2])@W2 + bias )
// A1 fp32 (bf16-converted at panel store); A2 bf16 (aggregation buffer).
// A panel: 128 rows x 32 k stored as 16 bf16x2 words/row, row stride AROW=20.
// Weight fragments K*64 uint32 in SMEM loaded once per CTA (persistent).
#define AROW 20
#define ABUF (128 * AROW)

__global__ void __launch_bounds__(256)
tc_gemm(const float* __restrict__ A1, int K1, const float* __restrict__ Wf1,
        const __nv_bfloat16* __restrict__ A2, int K2, const float* __restrict__ Wf2,
        const float* __restrict__ rowscale, const float* __restrict__ bias,
        float* __restrict__ C, __nv_bfloat16* __restrict__ Cb16,
        int M, int act) {
    extern __shared__ float smem[];
    int KT = K1 + K2;
    float* sW = smem;                         // KT*64 uint32 (fragment order)
    float* sA = smem + (size_t)KT * 64;       // ABUF uint32
    float* sB = sA + ABUF;                    // 128 floats bias

    int t = threadIdx.x, warp = t >> 5, lane = t & 31;
    int wm = (warp & 3) * 32;   // warp row offset
    int wn = (warp >> 2) * 64;  // warp col offset
    bool haveScale = (rowscale != nullptr);

    // one-time: weight fragments + bias to SMEM (K*16 float4 per matrix)
    {
        const float4* s1 = (const float4*)Wf1;
        float4* d = (float4*)sW;
        for (int i = t; i < K1 * 16; i += 256) d[i] = s1[i];
        if (K2 > 0) {
            const float4* s2 = (const float4*)Wf2;
            float4* d2 = (float4*)(sW + (size_t)K1 * 64);
            for (int i = t; i < K2 * 16; i += 256) d2[i] = s2[i];
        }
        if (t < 128) sB[t] = bias[t];
    }
    __syncthreads();

    int nMB = (M + 127) >> 7;
    int nP = KT >> 5;

    // panel-load mapping: rows lrow + j*32 (j=0..3), elements lc4..lc4+3
    int lrow = t >> 3;         // 0..31
    int lc4 = (t & 7) * 4;     // element offset 0..28 (pair offset lc4/2)

    for (int mb = blockIdx.x; mb < nMB; mb += gridDim.x) {
        int bm = mb << 7;

        float acc[2][8][4];
#pragma unroll
        for (int a = 0; a < 2; a++)
#pragma unroll
            for (int b = 0; b < 8; b++)
#pragma unroll
                for (int c = 0; c < 4; c++) acc[a][b][c] = 0.f;

        // prefetch panel 0 into registers
        float4 rv[4];
#pragma unroll
        for (int j = 0; j < 4; j++) {
            int row = lrow + j * 32;
            int grow = bm + row;
            float4 v = make_float4(0.f, 0.f, 0.f, 0.f);
            if (grow < M) {
                if (K1 > 0) {
                    v = *(const float4*)(A1 + (size_t)grow * K1 + lc4);
                } else {
                    uint2 u = *(const uint2*)(A2 + (size_t)grow * K2 + lc4);
                    float2 p0 = __bfloat1622float2(*(__nv_bfloat162*)&u.x);
                    float2 p1 = __bfloat1622float2(*(__nv_bfloat162*)&u.y);
                    float s = haveScale ? rowscale[grow] : 1.0f;
                    v = make_float4(p0.x * s, p0.y * s, p1.x * s, p1.y * s);
                }
            }
            rv[j] = v;
        }

        for (int p = 0; p < nP; p++) {
            __syncthreads();   // previous panel's mma done -> sA free
#pragma unroll
            for (int j = 0; j < 4; j++) {
                int row = lrow + j * 32;
                uint32_t* st = (uint32_t*)sA + row * AROW + (lc4 >> 1);
                st[0] = pack_bf16x2(rv[j].x, rv[j].y);
                st[1] = pack_bf16x2(rv[j].z, rv[j].w);
            }
            __syncthreads();   // panel visible

            // prefetch next panel into registers (latency hidden by mma below)
            if (p + 1 < nP) {
                int kt = (p + 1) << 5;
#pragma unroll
                for (int j = 0; j < 4; j++) {
                    int row = lrow + j * 32;
                    int grow = bm + row;
                    float4 v = make_float4(0.f, 0.f, 0.f, 0.f);
                    if (grow < M) {
                        if (kt < K1) {
                            v = *(const float4*)(A1 + (size_t)grow * K1 + kt + lc4);
                        } else {
                            int kp = kt - K1;
                            uint2 u = *(const uint2*)(A2 + (size_t)grow * K2 + kp + lc4);
                            float2 p0 = __bfloat1622float2(*(__nv_bfloat162*)&u.x);
                            float2 p1 = __bfloat1622float2(*(__nv_bfloat162*)&u.y);
                            float s = haveScale ? rowscale[grow] : 1.0f;
                            v = make_float4(p0.x * s, p0.y * s, p1.x * s, p1.y * s);
                        }
                    }
                    rv[j] = v;
                }
            }

            const uint32_t* aB = (const uint32_t*)sA;
#pragma unroll
            for (int ks = 0; ks < 2; ks++) {           // 2 x k16 per 32-K panel
                int kst = p * 2 + ks;                  // global k16 step
                uint2 bf[8];
                const uint2* wf = ((const uint2*)sW) + ((size_t)kst * 16 + (wn >> 3)) * 32 + lane;
#pragma unroll
                for (int j = 0; j < 8; j++) bf[j] = wf[j * 32];

#pragma unroll
                for (int mt = 0; mt < 2; mt++) {
                    int r = wm + mt * 16 + (lane >> 2);
                    int c = ks * 8 + (lane & 3);       // pair index
                    uint32_t a0 = aB[r * AROW + c];
                    uint32_t a1 = aB[(r + 8) * AROW + c];
                    uint32_t a2 = aB[r * AROW + c + 4];
                    uint32_t a3 = aB[(r + 8) * AROW + c + 4];
#pragma unroll
                    for (int nt = 0; nt < 8; nt++)
                        mma_bf16(acc[mt][nt], a0, a1, a2, a3, bf[nt].x, bf[nt].y);
                }
            }
        }

        // epilogue: bias + relu; fp32 stores + optional bf16 dual store
#pragma unroll
        for (int mt = 0; mt < 2; mt++) {
            int r0 = bm + wm + mt * 16 + (lane >> 2);
#pragma unroll
            for (int nt = 0; nt < 8; nt++) {
                int col = wn + nt * 8 + (lane & 3) * 2;
                float b0 = sB[col], b1 = sB[col + 1];
                float v0 = acc[mt][nt][0] + b0;
                float v1 = acc[mt][nt][1] + b1;
                float v2 = acc[mt][nt][2] + b0;
                float v3 = acc[mt][nt][3] + b1;
                if (act) {
                    v0 = fmaxf(v0, 0.f); v1 = fmaxf(v1, 0.f);
                    v2 = fmaxf(v2, 0.f); v3 = fmaxf(v3, 0.f);
                }
                if (r0 < M) {
                    *(float2*)(C + (size_t)r0 * 128 + col) = make_float2(v0, v1);
                    if (Cb16) *(uint32_t*)(Cb16 + (size_t)r0 * 128 + col) = pack_bf16x2(v0, v1);
                }
                if (r0 + 8 < M) {
                    *(float2*)(C + (size_t)(r0 + 8) * 128 + col) = make_float2(v2, v3);
                    if (Cb16) *(uint32_t*)(Cb16 + (size_t)(r0 + 8) * 128 + col) = pack_bf16x2(v2, v3);
                }
            }
        }
    }
}

// -------- dist path layer0: y0 = relu(e[N,5] @ W0[5,128] + b0) --------
__global__ void dist0_kernel(const float* __restrict__ e, const float* __restrict__ W0,
                             const float* __restrict__ b0, float* __restrict__ out, int n) {
    __shared__ float sW[5 * 128];
    __shared__ float sb[128];
    int t = threadIdx.x;  // 128
    for (int i = t; i < 5 * 128; i += 128) sW[i] = W0[i];
    sb[t] = b0[t];
    __syncthreads();
    for (long long nd = blockIdx.x; nd < n; nd += gridDim.x) {
        const float* ev = e + nd * 5;
        float v = sb[t];
        v += ev[0] * sW[0 * 128 + t];
        v += ev[1] * sW[1 * 128 + t];
        v += ev[2] * sW[2 * 128 + t];
        v += ev[3] * sW[3 * 128 + t];
        v += ev[4] * sW[4 * 128 + t];
        out[nd * 128 + t] = fmaxf(v, 0.f);
    }
}

// -------- final: out[n] = sigmoid(feat.fW[0:128] + dist.fW[128:256] + fb) --------
__global__ void final_kernel(const float* __restrict__ feat, const float* __restrict__ dist,
                             const float* __restrict__ fW, const float* __restrict__ fb,
                             float* __restrict__ out, int n) {
    long long wg = (long long)blockIdx.x * 8 + (threadIdx.x >> 5);
    int lane = threadIdx.x & 31;
    if (wg >= n) return;
    float4 f = *(const float4*)(feat + wg * 128 + lane * 4);
    float4 w1 = *(const float4*)(fW + lane * 4);
    float4 d = *(const float4*)(dist + wg * 128 + lane * 4);
    float4 w2 = *(const float4*)(fW + 128 + lane * 4);
    float s = f.x * w1.x + f.y * w1.y + f.z * w1.z + f.w * w1.w
            + d.x * w2.x + d.y * w2.y + d.z * w2.z + d.w * w2.w;
#pragma unroll
    for (int off = 16; off; off >>= 1) s += __shfl_xor_sync(0xFFFFFFFFu, s, off);
    if (lane == 0) {
        float z = s + fb[0];
        out[wg] = 1.0f / (1.0f + expf(-z));
    }
}

extern "C" void kernel_launch(void* const* d_in, const int* in_sizes, int n_in,
                              void* d_out, int out_size) {
    const float* x          = (const float*)d_in[0];
    const void*  ei         = d_in[1];
    const float* eattr      = (const float*)d_in[2];
    const float* pre_W      = (const float*)d_in[3];
    const float* pre_b      = (const float*)d_in[4];
    const float* c1_Ws      = (const float*)d_in[5];
    const float* c1_Wn      = (const float*)d_in[6];
    const float* c1_b       = (const float*)d_in[7];
    const float* c2_Ws      = (const float*)d_in[8];
    const float* c2_Wn      = (const float*)d_in[9];
    const float* c2_b       = (const float*)d_in[10];
    const float* nodepost_W = (const float*)d_in[11];
    const float* nodepost_b = (const float*)d_in[12];
    const float* d_W0       = (const float*)d_in[13];
    const float* d_b0       = (const float*)d_in[14];
    const float* d_W1       = (const float*)d_in[15];
    const float* d_b1       = (const float*)d_in[16];
    const float* d_W2       = (const float*)d_in[17];
    const float* d_b2       = (const float*)d_in[18];
    const float* d_W3       = (const float*)d_in[19];
    const float* d_b3       = (const float*)d_in[20];
    const float* final_W    = (const float*)d_in[21];
    const float* final_b    = (const float*)d_in[22];
    float* out = (float*)d_out;

    int n = in_sizes[0] / FIN;
    long long E = (long long)in_sizes[1] / 2;

    float *bufA, *bufB, *bufC, *deg, *wbuf;
    __nv_bfloat16 *hb16, *aggb16;
    cudaGetSymbolAddress((void**)&bufA, g_bufA);
    cudaGetSymbolAddress((void**)&bufB, g_bufB);
    cudaGetSymbolAddress((void**)&bufC, g_bufC);
    cudaGetSymbolAddress((void**)&deg, g_deg);
    cudaGetSymbolAddress((void**)&wbuf, g_wbuf);
    cudaGetSymbolAddress((void**)&hb16, g_hb16);
    cudaGetSymbolAddress((void**)&aggb16, g_aggb16);

    // fragment buffer layout (uint2 fragments; sizes in floats)
    float* f_pre  = wbuf;                  // K=256 -> 16384 floats
    float* f_c1s  = wbuf + 16384;          // K=128 -> 8192 each
    float* f_c1n  = f_c1s + 8192;
    float* f_c2s  = f_c1n + 8192;
    float* f_c2n  = f_c2s + 8192;
    float* f_np   = f_c2n + 8192;
    float* f_d1   = f_np + 8192;
    float* f_d2   = f_d1 + 8192;
    float* f_d3   = f_d2 + 8192;

    const int SMEM_K256 = (256 * 64 + ABUF + 128) * 4;  // ~76 KB
    const int SMEM_K128 = (128 * 64 + ABUF + 128) * 4;  // ~43 KB
    cudaFuncSetAttribute(tc_gemm, cudaFuncAttributeMaxDynamicSharedMemorySize, SMEM_K256);

    const int nSM = 148;   // B200 (sm_100a)
    int nMB = (n + 127) / 128;
    int gemm_grid = nSM < nMB ? nSM : nMB;
    int gemm_grid2 = (2 * nSM) < nMB ? (2 * nSM) : nMB;

    long long aggz4 = (long long)n * 16;          // n*128 bf16 = n*16 float4
    int scat_grid = (int)((E + 15) / 16);

    detect_idx64_kernel<<<1, 1024>>>((const unsigned int*)ei);

    // weight fragment prep: ONE launch for all 9 weights
    {
        dim3 g(32, 9);   // K=256 needs 8192 threads = 32 blocks; K=128 guarded
        prepW_all<<<g, 256>>>(pre_W, c1_Ws, c1_Wn, c2_Ws, c2_Wn,
                              nodepost_W, d_W1, d_W2, d_W3, wbuf);
    }

    zero_kernel<<<(int)((n / 4 + 255) / 256) + 1, 256>>>(deg, (n + 3) / 4);
    deg_kernel<<<(int)((E + 255) / 256), 256>>>(ei, E);
    deginv_kernel<<<(n + 255) / 256, 256>>>(n);

    // pre: h0 = x @ pre_W + pre_b  -> bufA (fp32) + hb16 (bf16)
    tc_gemm<<<gemm_grid, 256, SMEM_K256>>>(x, FIN, f_pre, nullptr, 0, nullptr, nullptr,
                                           pre_b, bufA, hb16, n, 0);

    // agg1 = scatter_b16(h0) -> aggb16
    zero_kernel<<<(int)((aggz4 + 255) / 256), 256>>>((float*)aggb16, aggz4);
    scatter_b16_kernel<<<scat_grid, 256>>>(hb16, aggb16, ei, E);

    // h1 = relu(h0@c1_Ws + deginv*agg1@c1_Wn + b) -> bufC (fp32) + hb16 (bf16)
    tc_gemm<<<gemm_grid, 256, SMEM_K256>>>(bufA, H, f_c1s, aggb16, H, f_c1n, deg,
                                           c1_b, bufC, hb16, n, 1);

    // agg2 = scatter_b16(h1) -> aggb16
    zero_kernel<<<(int)((aggz4 + 255) / 256), 256>>>((float*)aggb16, aggz4);
    scatter_b16_kernel<<<scat_grid, 256>>>(hb16, aggb16, ei, E);

    // h2 = relu(h1@c2_Ws + deginv*agg2@c2_Wn + b) -> bufA
    tc_gemm<<<gemm_grid, 256, SMEM_K256>>>(bufC, H, f_c2s, aggb16, H, f_c2n, deg,
                                           c2_b, bufA, nullptr, n, 1);

    // feat = h2 @ nodepost_W + b -> bufC
    tc_gemm<<<gemm_grid2, 256, SMEM_K128>>>(bufA, H, f_np, nullptr, 0, nullptr, nullptr,
                                            nodepost_b, bufC, nullptr, n, 0);

    // dist path: y0 -> bufB, then 3 GEMMs ping-pong (fp32)
    dist0_kernel<<<2048, 128>>>(eattr, d_W0, d_b0, bufB, n);
    tc_gemm<<<gemm_grid2, 256, SMEM_K128>>>(bufB, H, f_d1, nullptr, 0, nullptr, nullptr,
                                            d_b1, bufA, nullptr, n, 1);
    tc_gemm<<<gemm_grid2, 256, SMEM_K128>>>(bufA, H, f_d2, nullptr, 0, nullptr, nullptr,
                                            d_b2, bufB, nullptr, n, 1);
    tc_gemm<<<gemm_grid2, 256, SMEM_K128>>>(bufB, H, f_d3, nullptr, 0, nullptr, nullptr,
                                            d_b3, bufA, nullptr, n, 0);

    final_kernel<<<(n + 7) / 8, 256>>>(bufC, bufA, final_W, final_b, out, n);
}

// round 13
// speedup vs baseline: 2.4683x; 1.0478x over previous
#include <cuda_runtime.h>
#include <cuda_bf16.h>
#include <math.h>
#include <cstdint>

// Problem constants (fixed shapes for this problem)
#define NMAX 100000
#define H 128
#define FIN 256

// -------- scratch (no allocation allowed) --------
__device__ float g_bufA[(size_t)NMAX * H];
__device__ float g_bufB[(size_t)NMAX * H];
__device__ float g_bufC[(size_t)NMAX * H];
__device__ float g_deg[NMAX];
__device__ float g_wbuf[16384 + 8 * 8192];           // bf16 weight fragments
__device__ float g_vfin[260];                        // fused final: v1[128] v2[128] c
__device__ __nv_bfloat16 g_hb16[(size_t)NMAX * H];   // bf16 copy of conv input h
__device__ __nv_bfloat16 g_aggb16[(size_t)NMAX * H]; // bf16 aggregation buffer
__device__ int   g_is64;

// ================ edge-index dtype detection ================
__global__ void detect_idx64_kernel(const unsigned int* __restrict__ ei) {
    int any = __syncthreads_or(ei[2 * threadIdx.x + 1] != 0u);
    if (threadIdx.x == 0) g_is64 = any ? 0 : 1;
}
__device__ __forceinline__ long long load_idx(const void* ei, long long i, int is64) {
    if (is64) return ((const long long*)ei)[i];
    return (long long)(((const int*)ei)[i]);
}

// ================ small kernels ================
__global__ void zero_kernel(float* __restrict__ p, long long n4) {
    long long i = (long long)blockIdx.x * blockDim.x + threadIdx.x;
    if (i < n4) ((float4*)p)[i] = make_float4(0.f, 0.f, 0.f, 0.f);
}
__global__ void deg_kernel(const void* __restrict__ ei, long long E) {
    long long e = (long long)blockIdx.x * blockDim.x + threadIdx.x;
    if (e >= E) return;
    int is64 = g_is64;
    long long dst = load_idx(ei, E + e, is64);
    atomicAdd(&g_deg[dst], 1.0f);
}
__global__ void deginv_kernel(int n) {
    int i = blockIdx.x * blockDim.x + threadIdx.x;
    if (i < n) g_deg[i] = 1.0f / fmaxf(g_deg[i], 1.0f);
}

// bf16 scatter-add: agg[dst] += h[src].
// HALF-WARP per edge: 16 lanes x 16B (v4.bf16x2).
__global__ void scatter_b16_kernel(const __nv_bfloat16* __restrict__ h,
                                   __nv_bfloat16* __restrict__ agg,
                                   const void* __restrict__ ei, long long E) {
    long long e = (long long)blockIdx.x * 16 + (threadIdx.x >> 4);
    int lane = threadIdx.x & 15;
    if (e >= E) return;
    int is64 = g_is64;
    long long src = load_idx(ei, e, is64);
    long long dst = load_idx(ei, E + e, is64);
    uint4 v = ((const uint4*)(h + src * H))[lane];            // 8 bf16
    __nv_bfloat16* p = agg + dst * H + lane * 8;
    asm volatile("red.global.add.noftz.v4.bf16x2 [%0], {%1, %2, %3, %4};"
                 :: "l"(p), "r"(v.x), "r"(v.y), "r"(v.z), "r"(v.w) : "memory");
}

// ================ bf16 helpers ================
__device__ __forceinline__ uint32_t pack_bf16x2(float lo, float hi) {
    uint32_t r;
    asm("cvt.rn.bf16x2.f32 %0, %1, %2;" : "=r"(r) : "f"(hi), "f"(lo));
    return r;
}
__device__ __forceinline__ void mma_bf16(float* c, uint32_t a0, uint32_t a1,
                                         uint32_t a2, uint32_t a3,
                                         uint32_t b0, uint32_t b1) {
    asm volatile(
        "mma.sync.aligned.m16n8k16.row.col.f32.bf16.bf16.f32 "
        "{%0,%1,%2,%3}, {%4,%5,%6,%7}, {%8,%9}, {%0,%1,%2,%3};"
        : "+f"(c[0]), "+f"(c[1]), "+f"(c[2]), "+f"(c[3])
        : "r"(a0), "r"(a1), "r"(a2), "r"(a3), "r"(b0), "r"(b1));
}

// ================ fused weight fragment preparation (one launch) ================
// m16n8k16 bf16 B-fragment order, uint2 out[kstep16][ntile][lane]:
//   b0 = {W[k0][n], W[k0+1][n]},  b1 = {W[k0+8][n], W[k0+9][n]}
//   with k0 = kstep*16 + (lane&3)*2,  n = ntile*8 + (lane>>2).
// Only 7 weights now (nodepost_W and d_W3 are folded into the final vectors).
__global__ void prepW_all(const float* W0, const float* W1, const float* W2,
                          const float* W3, const float* W4, const float* W5,
                          const float* W6, float* __restrict__ wbuf) {
    int wid = blockIdx.y;
    const float* W; float* dst; int K;
    switch (wid) {
        case 0: W = W0; dst = wbuf;                K = 256; break;
        case 1: W = W1; dst = wbuf + 16384;        K = 128; break;
        case 2: W = W2; dst = wbuf + 16384 + 8192; K = 128; break;
        case 3: W = W3; dst = wbuf + 16384 + 2 * 8192; K = 128; break;
        case 4: W = W4; dst = wbuf + 16384 + 3 * 8192; K = 128; break;
        case 5: W = W5; dst = wbuf + 16384 + 4 * 8192; K = 128; break;
        default: W = W6; dst = wbuf + 16384 + 5 * 8192; K = 128; break;
    }
    int idx = blockIdx.x * blockDim.x + threadIdx.x;
    int total = (K >> 4) * 16 * 32;
    if (idx >= total) return;
    int lane = idx & 31;
    int ntile = (idx >> 5) & 15;
    int kstep = idx >> 9;
    int k0 = kstep * 16 + (lane & 3) * 2;
    int nn = ntile * 8 + (lane >> 2);
    uint32_t b0 = pack_bf16x2(W[k0 * 128 + nn], W[(k0 + 1) * 128 + nn]);
    uint32_t b1 = pack_bf16x2(W[(k0 + 8) * 128 + nn], W[(k0 + 9) * 128 + nn]);
    ((uint2*)dst)[idx] = make_uint2(b0, b1);
}

// ================ fold final_W through nodepost_W / d_W3 (exact fp32) ================
// v1[k] = sum_j npW[k][j] * fW[j];  v2[k] = sum_j d3W[k][j] * fW[128+j]
// c = np_b.fW[0:128] + d3_b.fW[128:256] + fb
__global__ void prep_final(const float* __restrict__ npW, const float* __restrict__ npb,
                           const float* __restrict__ d3W, const float* __restrict__ d3b,
                           const float* __restrict__ fW, const float* __restrict__ fb,
                           float* __restrict__ v) {
    __shared__ float sw[256];
    __shared__ float red[128];
    int t = threadIdx.x;  // 128
    sw[t] = fW[t];
    sw[t + 128] = fW[t + 128];
    __syncthreads();
    float s1 = 0.f, s2 = 0.f;
#pragma unroll 8
    for (int j = 0; j < 128; j++) {
        s1 += npW[t * 128 + j] * sw[j];
        s2 += d3W[t * 128 + j] * sw[128 + j];
    }
    v[t] = s1;
    v[128 + t] = s2;
    red[t] = npb[t] * sw[t] + d3b[t] * sw[128 + t];
    __syncthreads();
    for (int off = 64; off; off >>= 1) {
        if (t < off) red[t] += red[t + off];
        __syncthreads();
    }
    if (t == 0) v[256] = red[0] + fb[0];
}

// ================ fused final: out = sigmoid(h2.v1 + y2.v2 + c) ================
__global__ void final_fused_kernel(const float* __restrict__ h2, const float* __restrict__ y2,
                                   const float* __restrict__ v, float* __restrict__ out, int n) {
    long long wg = (long long)blockIdx.x * 8 + (threadIdx.x >> 5);
    int lane = threadIdx.x & 31;
    if (wg >= n) return;
    float4 f = *(const float4*)(h2 + wg * 128 + lane * 4);
    float4 w1 = *(const float4*)(v + lane * 4);
    float4 d = *(const float4*)(y2 + wg * 128 + lane * 4);
    float4 w2 = *(const float4*)(v + 128 + lane * 4);
    float s = f.x * w1.x + f.y * w1.y + f.z * w1.z + f.w * w1.w
            + d.x * w2.x + d.y * w2.y + d.z * w2.z + d.w * w2.w;
#pragma unroll
    for (int off = 16; off; off >>= 1) s += __shfl_xor_sync(0xFFFFFFFFu, s, off);
    if (lane == 0) {
        float z = s + v[256];
        out[wg] = 1.0f / (1.0f + expf(-z));
    }
}

// ================ persistent tensor-core GEMM (bf16 m16n8k16) ================
// C[M,128] = act( A1[M,K1]@W1 + (rowscale ⊙ A2b16[M,K2])@W2 + bias )
// A1 fp32 (bf16-converted at panel store); A2 bf16 (aggregation buffer).
// A panel: 128 rows x 32 k stored as 16 bf16x2 words/row, row stride AROW=20.
#define AROW 20
#define ABUF (128 * AROW)

__global__ void __launch_bounds__(256)
tc_gemm(const float* __restrict__ A1, int K1, const float* __restrict__ Wf1,
        const __nv_bfloat16* __restrict__ A2, int K2, const float* __restrict__ Wf2,
        const float* __restrict__ rowscale, const float* __restrict__ bias,
        float* __restrict__ C, __nv_bfloat16* __restrict__ Cb16,
        int M, int act) {
    extern __shared__ float smem[];
    int KT = K1 + K2;
    float* sW = smem;                         // KT*64 uint32 (fragment order)
    float* sA = smem + (size_t)KT * 64;       // ABUF uint32
    float* sB = sA + ABUF;                    // 128 floats bias

    int t = threadIdx.x, warp = t >> 5, lane = t & 31;
    int wm = (warp & 3) * 32;   // warp row offset
    int wn = (warp >> 2) * 64;  // warp col offset
    bool haveScale = (rowscale != nullptr);

    // one-time: weight fragments + bias to SMEM (K*16 float4 per matrix)
    {
        const float4* s1 = (const float4*)Wf1;
        float4* d = (float4*)sW;
        for (int i = t; i < K1 * 16; i += 256) d[i] = s1[i];
        if (K2 > 0) {
            const float4* s2 = (const float4*)Wf2;
            float4* d2 = (float4*)(sW + (size_t)K1 * 64);
            for (int i = t; i < K2 * 16; i += 256) d2[i] = s2[i];
        }
        if (t < 128) sB[t] = bias[t];
    }
    __syncthreads();

    int nMB = (M + 127) >> 7;
    int nP = KT >> 5;

    // panel-load mapping: rows lrow + j*32 (j=0..3), elements lc4..lc4+3
    int lrow = t >> 3;         // 0..31
    int lc4 = (t & 7) * 4;     // element offset 0..28 (pair offset lc4/2)

    for (int mb = blockIdx.x; mb < nMB; mb += gridDim.x) {
        int bm = mb << 7;

        float acc[2][8][4];
#pragma unroll
        for (int a = 0; a < 2; a++)
#pragma unroll
            for (int b = 0; b < 8; b++)
#pragma unroll
                for (int c = 0; c < 4; c++) acc[a][b][c] = 0.f;

        // prefetch panel 0 into registers
        float4 rv[4];
#pragma unroll
        for (int j = 0; j < 4; j++) {
            int row = lrow + j * 32;
            int grow = bm + row;
            float4 v = make_float4(0.f, 0.f, 0.f, 0.f);
            if (grow < M) {
                if (K1 > 0) {
                    v = *(const float4*)(A1 + (size_t)grow * K1 + lc4);
                } else {
                    uint2 u = *(const uint2*)(A2 + (size_t)grow * K2 + lc4);
                    float2 p0 = __bfloat1622float2(*(__nv_bfloat162*)&u.x);
                    float2 p1 = __bfloat1622float2(*(__nv_bfloat162*)&u.y);
                    float s = haveScale ? rowscale[grow] : 1.0f;
                    v = make_float4(p0.x * s, p0.y * s, p1.x * s, p1.y * s);
                }
            }
            rv[j] = v;
        }

        for (int p = 0; p < nP; p++) {
            __syncthreads();   // previous panel's mma done -> sA free
#pragma unroll
            for (int j = 0; j < 4; j++) {
                int row = lrow + j * 32;
                uint32_t* st = (uint32_t*)sA + row * AROW + (lc4 >> 1);
                st[0] = pack_bf16x2(rv[j].x, rv[j].y);
                st[1] = pack_bf16x2(rv[j].z, rv[j].w);
            }
            __syncthreads();   // panel visible

            // prefetch next panel into registers (latency hidden by mma below)
            if (p + 1 < nP) {
                int kt = (p + 1) << 5;
#pragma unroll
                for (int j = 0; j < 4; j++) {
                    int row = lrow + j * 32;
                    int grow = bm + row;
                    float4 v = make_float4(0.f, 0.f, 0.f, 0.f);
                    if (grow < M) {
                        if (kt < K1) {
                            v = *(const float4*)(A1 + (size_t)grow * K1 + kt + lc4);
                        } else {
                            int kp = kt - K1;
                            uint2 u = *(const uint2*)(A2 + (size_t)grow * K2 + kp + lc4);
                            float2 p0 = __bfloat1622float2(*(__nv_bfloat162*)&u.x);
                            float2 p1 = __bfloat1622float2(*(__nv_bfloat162*)&u.y);
                            float s = haveScale ? rowscale[grow] : 1.0f;
                            v = make_float4(p0.x * s, p0.y * s, p1.x * s, p1.y * s);
                        }
                    }
                    rv[j] = v;
                }
            }

            const uint32_t* aB = (const uint32_t*)sA;
#pragma unroll
            for (int ks = 0; ks < 2; ks++) {           // 2 x k16 per 32-K panel
                int kst = p * 2 + ks;                  // global k16 step
                uint2 bf[8];
                const uint2* wf = ((const uint2*)sW) + ((size_t)kst * 16 + (wn >> 3)) * 32 + lane;
#pragma unroll
                for (int j = 0; j < 8; j++) bf[j] = wf[j * 32];

#pragma unroll
                for (int mt = 0; mt < 2; mt++) {
                    int r = wm + mt * 16 + (lane >> 2);
                    int c = ks * 8 + (lane & 3);       // pair index
                    uint32_t a0 = aB[r * AROW + c];
                    uint32_t a1 = aB[(r + 8) * AROW + c];
                    uint32_t a2 = aB[r * AROW + c + 4];
                    uint32_t a3 = aB[(r + 8) * AROW + c + 4];
#pragma unroll
                    for (int nt = 0; nt < 8; nt++)
                        mma_bf16(acc[mt][nt], a0, a1, a2, a3, bf[nt].x, bf[nt].y);
                }
            }
        }

        // epilogue: bias + relu; fp32 stores + optional bf16 dual store
#pragma unroll
        for (int mt = 0; mt < 2; mt++) {
            int r0 = bm + wm + mt * 16 + (lane >> 2);
#pragma unroll
            for (int nt = 0; nt < 8; nt++) {
                int col = wn + nt * 8 + (lane & 3) * 2;
                float b0 = sB[col], b1 = sB[col + 1];
                float v0 = acc[mt][nt][0] + b0;
                float v1 = acc[mt][nt][1] + b1;
                float v2 = acc[mt][nt][2] + b0;
                float v3 = acc[mt][nt][3] + b1;
                if (act) {
                    v0 = fmaxf(v0, 0.f); v1 = fmaxf(v1, 0.f);
                    v2 = fmaxf(v2, 0.f); v3 = fmaxf(v3, 0.f);
                }
                if (r0 < M) {
                    *(float2*)(C + (size_t)r0 * 128 + col) = make_float2(v0, v1);
                    if (Cb16) *(uint32_t*)(Cb16 + (size_t)r0 * 128 + col) = pack_bf16x2(v0, v1);
                }
                if (r0 + 8 < M) {
                    *(float2*)(C + (size_t)(r0 + 8) * 128 + col) = make_float2(v2, v3);
                    if (Cb16) *(uint32_t*)(Cb16 + (size_t)(r0 + 8) * 128 + col) = pack_bf16x2(v2, v3);
                }
            }
        }
    }
}

// -------- dist path layer0: y0 = relu(e[N,5] @ W0[5,128] + b0) --------
__global__ void dist0_kernel(const float* __restrict__ e, const float* __restrict__ W0,
                             const float* __restrict__ b0, float* __restrict__ out, int n) {
    __shared__ float sW[5 * 128];
    __shared__ float sb[128];
    int t = threadIdx.x;  // 128
    for (int i = t; i < 5 * 128; i += 128) sW[i] = W0[i];
    sb[t] = b0[t];
    __syncthreads();
    for (long long nd = blockIdx.x; nd < n; nd += gridDim.x) {
        const float* ev = e + nd * 5;
        float v = sb[t];
        v += ev[0] * sW[0 * 128 + t];
        v += ev[1] * sW[1 * 128 + t];
        v += ev[2] * sW[2 * 128 + t];
        v += ev[3] * sW[3 * 128 + t];
        v += ev[4] * sW[4 * 128 + t];
        out[nd * 128 + t] = fmaxf(v, 0.f);
    }
}

extern "C" void kernel_launch(void* const* d_in, const int* in_sizes, int n_in,
                              void* d_out, int out_size) {
    const float* x          = (const float*)d_in[0];
    const void*  ei         = d_in[1];
    const float* eattr      = (const float*)d_in[2];
    const float* pre_W      = (const float*)d_in[3];
    const float* pre_b      = (const float*)d_in[4];
    const float* c1_Ws      = (const float*)d_in[5];
    const float* c1_Wn      = (const float*)d_in[6];
    const float* c1_b       = (const float*)d_in[7];
    const float* c2_Ws      = (const float*)d_in[8];
    const float* c2_Wn      = (const float*)d_in[9];
    const float* c2_b       = (const float*)d_in[10];
    const float* nodepost_W = (const float*)d_in[11];
    const float* nodepost_b = (const float*)d_in[12];
    const float* d_W0       = (const float*)d_in[13];
    const float* d_b0       = (const float*)d_in[14];
    const float* d_W1       = (const float*)d_in[15];
    const float* d_b1       = (const float*)d_in[16];
    const float* d_W2       = (const float*)d_in[17];
    const float* d_b2       = (const float*)d_in[18];
    const float* d_W3       = (const float*)d_in[19];
    const float* d_b3       = (const float*)d_in[20];
    const float* final_W    = (const float*)d_in[21];
    const float* final_b    = (const float*)d_in[22];
    float* out = (float*)d_out;

    int n = in_sizes[0] / FIN;
    long long E = (long long)in_sizes[1] / 2;

    float *bufA, *bufB, *bufC, *deg, *wbuf, *vfin;
    __nv_bfloat16 *hb16, *aggb16;
    cudaGetSymbolAddress((void**)&bufA, g_bufA);
    cudaGetSymbolAddress((void**)&bufB, g_bufB);
    cudaGetSymbolAddress((void**)&bufC, g_bufC);
    cudaGetSymbolAddress((void**)&deg, g_deg);
    cudaGetSymbolAddress((void**)&wbuf, g_wbuf);
    cudaGetSymbolAddress((void**)&vfin, g_vfin);
    cudaGetSymbolAddress((void**)&hb16, g_hb16);
    cudaGetSymbolAddress((void**)&aggb16, g_aggb16);

    // fragment buffer layout (uint2 fragments; sizes in floats)
    float* f_pre  = wbuf;                  // K=256 -> 16384 floats
    float* f_c1s  = wbuf + 16384;          // K=128 -> 8192 each
    float* f_c1n  = f_c1s + 8192;
    float* f_c2s  = f_c1n + 8192;
    float* f_c2n  = f_c2s + 8192;
    float* f_d1   = f_c2n + 8192;
    float* f_d2   = f_d1 + 8192;

    const int SMEM_K256 = (256 * 64 + ABUF + 128) * 4;  // ~76 KB
    const int SMEM_K128 = (128 * 64 + ABUF + 128) * 4;  // ~43 KB
    cudaFuncSetAttribute(tc_gemm, cudaFuncAttributeMaxDynamicSharedMemorySize, SMEM_K256);

    const int nSM = 148;   // B200 (sm_100a)
    int nMB = (n + 127) / 128;
    int gemm_grid = nSM < nMB ? nSM : nMB;
    int gemm_grid2 = (2 * nSM) < nMB ? (2 * nSM) : nMB;

    long long aggz4 = (long long)n * 16;          // n*128 bf16 = n*16 float4
    int scat_grid = (int)((E + 15) / 16);

    detect_idx64_kernel<<<1, 1024>>>((const unsigned int*)ei);

    // weight fragment prep: ONE launch for 7 weights (np_W, d_W3 folded away)
    {
        dim3 g(32, 7);
        prepW_all<<<g, 256>>>(pre_W, c1_Ws, c1_Wn, c2_Ws, c2_Wn, d_W1, d_W2, wbuf);
    }
    // fold final_W through nodepost_W / d_W3 (exact)
    prep_final<<<1, 128>>>(nodepost_W, nodepost_b, d_W3, d_b3, final_W, final_b, vfin);

    zero_kernel<<<(int)((n / 4 + 255) / 256) + 1, 256>>>(deg, (n + 3) / 4);
    deg_kernel<<<(int)((E + 255) / 256), 256>>>(ei, E);
    deginv_kernel<<<(n + 255) / 256, 256>>>(n);

    // ---- dist path first: y0 -> bufB, y1 -> bufC, y2 -> bufB ----
    dist0_kernel<<<2048, 128>>>(eattr, d_W0, d_b0, bufB, n);
    tc_gemm<<<gemm_grid2, 256, SMEM_K128>>>(bufB, H, f_d1, nullptr, 0, nullptr, nullptr,
                                            d_b1, bufC, nullptr, n, 1);
    tc_gemm<<<gemm_grid2, 256, SMEM_K128>>>(bufC, H, f_d2, nullptr, 0, nullptr, nullptr,
                                            d_b2, bufB, nullptr, n, 1);
    // bufB = y2, kept alive to the end

    // ---- feat path ----
    // pre: h0 = x @ pre_W + pre_b  -> bufA (fp32) + hb16 (bf16)
    tc_gemm<<<gemm_grid, 256, SMEM_K256>>>(x, FIN, f_pre, nullptr, 0, nullptr, nullptr,
                                           pre_b, bufA, hb16, n, 0);

    // agg1 = scatter_b16(h0) -> aggb16
    zero_kernel<<<(int)((aggz4 + 255) / 256), 256>>>((float*)aggb16, aggz4);
    scatter_b16_kernel<<<scat_grid, 256>>>(hb16, aggb16, ei, E);

    // h1 = relu(h0@c1_Ws + deginv*agg1@c1_Wn + b) -> bufC (fp32) + hb16 (bf16)
    tc_gemm<<<gemm_grid, 256, SMEM_K256>>>(bufA, H, f_c1s, aggb16, H, f_c1n, deg,
                                           c1_b, bufC, hb16, n, 1);

    // agg2 = scatter_b16(h1) -> aggb16
    zero_kernel<<<(int)((aggz4 + 255) / 256), 256>>>((float*)aggb16, aggz4);
    scatter_b16_kernel<<<scat_grid, 256>>>(hb16, aggb16, ei, E);

    // h2 = relu(h1@c2_Ws + deginv*agg2@c2_Wn + b) -> bufA
    tc_gemm<<<gemm_grid, 256, SMEM_K256>>>(bufC, H, f_c2s, aggb16, H, f_c2n, deg,
                                           c2_b, bufA, nullptr, n, 1);

    // fused final: out = sigmoid(h2.v1 + y2.v2 + c)
    final_fused_kernel<<<(n + 7) / 8, 256>>>(bufA, bufB, vfin, out, n);
}

// round 14
// speedup vs baseline: 2.5778x; 1.0444x over previous
#include <cuda_runtime.h>
#include <cuda_bf16.h>
#include <math.h>
#include <cstdint>

// Problem constants (fixed shapes for this problem)
#define NMAX 100000
#define H 128
#define FIN 256

// -------- scratch (no allocation allowed) --------
__device__ float g_bufA[(size_t)NMAX * H];
__device__ float g_bufB[(size_t)NMAX * H];
__device__ float g_bufC[(size_t)NMAX * H];
__device__ float g_deg[NMAX];
__device__ float g_wbuf[16384 + 8 * 8192];           // bf16 weight fragments
__device__ float g_vfin[260];                        // fused final: v1[128] v2[128] c
__device__ __nv_bfloat16 g_hb16[(size_t)NMAX * H];   // bf16 hidden state (h0/h1 in place)
__device__ __nv_bfloat16 g_aggb16[(size_t)NMAX * H]; // bf16 aggregation buffer
__device__ int   g_is64;

// ================ edge-index dtype detection ================
__global__ void detect_idx64_kernel(const unsigned int* __restrict__ ei) {
    int any = __syncthreads_or(ei[2 * threadIdx.x + 1] != 0u);
    if (threadIdx.x == 0) g_is64 = any ? 0 : 1;
}
__device__ __forceinline__ long long load_idx(const void* ei, long long i, int is64) {
    if (is64) return ((const long long*)ei)[i];
    return (long long)(((const int*)ei)[i]);
}

// ================ small kernels ================
__global__ void zero_kernel(float* __restrict__ p, long long n4) {
    long long i = (long long)blockIdx.x * blockDim.x + threadIdx.x;
    if (i < n4) ((float4*)p)[i] = make_float4(0.f, 0.f, 0.f, 0.f);
}
__global__ void deg_kernel(const void* __restrict__ ei, long long E) {
    long long e = (long long)blockIdx.x * blockDim.x + threadIdx.x;
    if (e >= E) return;
    int is64 = g_is64;
    long long dst = load_idx(ei, E + e, is64);
    atomicAdd(&g_deg[dst], 1.0f);
}

// bf16 scatter-add: agg[dst] += h[src].
// HALF-WARP per edge: 16 lanes x 16B (v4.bf16x2).
__global__ void scatter_b16_kernel(const __nv_bfloat16* __restrict__ h,
                                   __nv_bfloat16* __restrict__ agg,
                                   const void* __restrict__ ei, long long E) {
    long long e = (long long)blockIdx.x * 16 + (threadIdx.x >> 4);
    int lane = threadIdx.x & 15;
    if (e >= E) return;
    int is64 = g_is64;
    long long src = load_idx(ei, e, is64);
    long long dst = load_idx(ei, E + e, is64);
    uint4 v = ((const uint4*)(h + src * H))[lane];            // 8 bf16
    __nv_bfloat16* p = agg + dst * H + lane * 8;
    asm volatile("red.global.add.noftz.v4.bf16x2 [%0], {%1, %2, %3, %4};"
                 :: "l"(p), "r"(v.x), "r"(v.y), "r"(v.z), "r"(v.w) : "memory");
}

// ================ bf16 helpers ================
__device__ __forceinline__ uint32_t pack_bf16x2(float lo, float hi) {
    uint32_t r;
    asm("cvt.rn.bf16x2.f32 %0, %1, %2;" : "=r"(r) : "f"(hi), "f"(lo));
    return r;
}
__device__ __forceinline__ void mma_bf16(float* c, uint32_t a0, uint32_t a1,
                                         uint32_t a2, uint32_t a3,
                                         uint32_t b0, uint32_t b1) {
    asm volatile(
        "mma.sync.aligned.m16n8k16.row.col.f32.bf16.bf16.f32 "
        "{%0,%1,%2,%3}, {%4,%5,%6,%7}, {%8,%9}, {%0,%1,%2,%3};"
        : "+f"(c[0]), "+f"(c[1]), "+f"(c[2]), "+f"(c[3])
        : "r"(a0), "r"(a1), "r"(a2), "r"(a3), "r"(b0), "r"(b1));
}

// ================ fused weight fragment preparation (one launch) ================
// m16n8k16 bf16 B-fragment order, uint2 out[kstep16][ntile][lane].
__global__ void prepW_all(const float* W0, const float* W1, const float* W2,
                          const float* W3, const float* W4, const float* W5,
                          const float* W6, float* __restrict__ wbuf) {
    int wid = blockIdx.y;
    const float* W; float* dst; int K;
    switch (wid) {
        case 0: W = W0; dst = wbuf;                K = 256; break;
        case 1: W = W1; dst = wbuf + 16384;        K = 128; break;
        case 2: W = W2; dst = wbuf + 16384 + 8192; K = 128; break;
        case 3: W = W3; dst = wbuf + 16384 + 2 * 8192; K = 128; break;
        case 4: W = W4; dst = wbuf + 16384 + 3 * 8192; K = 128; break;
        case 5: W = W5; dst = wbuf + 16384 + 4 * 8192; K = 128; break;
        default: W = W6; dst = wbuf + 16384 + 5 * 8192; K = 128; break;
    }
    int idx = blockIdx.x * blockDim.x + threadIdx.x;
    int total = (K >> 4) * 16 * 32;
    if (idx >= total) return;
    int lane = idx & 31;
    int ntile = (idx >> 5) & 15;
    int kstep = idx >> 9;
    int k0 = kstep * 16 + (lane & 3) * 2;
    int nn = ntile * 8 + (lane >> 2);
    uint32_t b0 = pack_bf16x2(W[k0 * 128 + nn], W[(k0 + 1) * 128 + nn]);
    uint32_t b1 = pack_bf16x2(W[(k0 + 8) * 128 + nn], W[(k0 + 9) * 128 + nn]);
    ((uint2*)dst)[idx] = make_uint2(b0, b1);
}

// ================ fold final_W through nodepost_W / d_W3 (exact fp32) ================
__global__ void prep_final(const float* __restrict__ npW, const float* __restrict__ npb,
                           const float* __restrict__ d3W, const float* __restrict__ d3b,
                           const float* __restrict__ fW, const float* __restrict__ fb,
                           float* __restrict__ v) {
    __shared__ float sw[256];
    __shared__ float red[128];
    int t = threadIdx.x;  // 128
    sw[t] = fW[t];
    sw[t + 128] = fW[t + 128];
    __syncthreads();
    float s1 = 0.f, s2 = 0.f;
#pragma unroll 8
    for (int j = 0; j < 128; j++) {
        s1 += npW[t * 128 + j] * sw[j];
        s2 += d3W[t * 128 + j] * sw[128 + j];
    }
    v[t] = s1;
    v[128 + t] = s2;
    red[t] = npb[t] * sw[t] + d3b[t] * sw[128 + t];
    __syncthreads();
    for (int off = 64; off; off >>= 1) {
        if (t < off) red[t] += red[t + off];
        __syncthreads();
    }
    if (t == 0) v[256] = red[0] + fb[0];
}

// ================ fused final: out = sigmoid(h2.v1 + y2.v2 + c) ================
__global__ void final_fused_kernel(const float* __restrict__ h2, const float* __restrict__ y2,
                                   const float* __restrict__ v, float* __restrict__ out, int n) {
    long long wg = (long long)blockIdx.x * 8 + (threadIdx.x >> 5);
    int lane = threadIdx.x & 31;
    if (wg >= n) return;
    float4 f = *(const float4*)(h2 + wg * 128 + lane * 4);
    float4 w1 = *(const float4*)(v + lane * 4);
    float4 d = *(const float4*)(y2 + wg * 128 + lane * 4);
    float4 w2 = *(const float4*)(v + 128 + lane * 4);
    float s = f.x * w1.x + f.y * w1.y + f.z * w1.z + f.w * w1.w
            + d.x * w2.x + d.y * w2.y + d.z * w2.z + d.w * w2.w;
#pragma unroll
    for (int off = 16; off; off >>= 1) s += __shfl_xor_sync(0xFFFFFFFFu, s, off);
    if (lane == 0) {
        float z = s + v[256];
        out[wg] = 1.0f / (1.0f + expf(-z));
    }
}

// ================ persistent tensor-core GEMM (bf16 m16n8k16) ================
// C = act( A1@W1 + (1/max(deg,1) ⊙ A2)@W2 + bias )
// First operand: A1f fp32 OR A1b bf16 (exactly one non-null if K1>0).
// A2 (if K2>0) is bf16, scaled by 1/max(deg,1) (raw degree, folded deginv).
// Outputs: Cf fp32 (nullable) and/or Cb16 bf16 (nullable; may alias A1b —
// CTA-row ownership makes in-place safe).
// zeroAgg (nullable): epilogue zeroes this buffer's rows [bm, bm+128)
// (all panel reads of those rows complete before the epilogue).
#define AROW 20
#define ABUF (128 * AROW)

__global__ void __launch_bounds__(256)
tc_gemm(const float* __restrict__ A1f, const __nv_bfloat16* __restrict__ A1b, int K1,
        const float* __restrict__ Wf1,
        const __nv_bfloat16* __restrict__ A2, int K2, const float* __restrict__ Wf2,
        const float* __restrict__ degraw, const float* __restrict__ bias,
        float* __restrict__ Cf, __nv_bfloat16* __restrict__ Cb16,
        __nv_bfloat16* __restrict__ zeroAgg,
        int M, int act) {
    extern __shared__ float smem[];
    int KT = K1 + K2;
    float* sW = smem;                         // KT*64 uint32 (fragment order)
    float* sA = smem + (size_t)KT * 64;       // ABUF uint32
    float* sB = sA + ABUF;                    // 128 floats bias

    int t = threadIdx.x, warp = t >> 5, lane = t & 31;
    int wm = (warp & 3) * 32;   // warp row offset
    int wn = (warp >> 2) * 64;  // warp col offset

    // one-time: weight fragments + bias to SMEM
    {
        const float4* s1 = (const float4*)Wf1;
        float4* d = (float4*)sW;
        for (int i = t; i < K1 * 16; i += 256) d[i] = s1[i];
        if (K2 > 0) {
            const float4* s2 = (const float4*)Wf2;
            float4* d2 = (float4*)(sW + (size_t)K1 * 64);
            for (int i = t; i < K2 * 16; i += 256) d2[i] = s2[i];
        }
        if (t < 128) sB[t] = bias[t];
    }
    __syncthreads();

    int nMB = (M + 127) >> 7;
    int nP = KT >> 5;

    int lrow = t >> 3;         // 0..31, actual rows lrow + j*32
    int lc4 = (t & 7) * 4;     // element offset 0..28

    for (int mb = blockIdx.x; mb < nMB; mb += gridDim.x) {
        int bm = mb << 7;

        float acc[2][8][4];
#pragma unroll
        for (int a = 0; a < 2; a++)
#pragma unroll
            for (int b = 0; b < 8; b++)
#pragma unroll
                for (int c = 0; c < 4; c++) acc[a][b][c] = 0.f;

        // panel prefetch helper (inlined twice below)
        float4 rv[4];
#pragma unroll
        for (int j = 0; j < 4; j++) {
            int row = lrow + j * 32;
            int grow = bm + row;
            float4 v = make_float4(0.f, 0.f, 0.f, 0.f);
            if (grow < M) {
                if (K1 > 0) {
                    if (A1f) {
                        v = *(const float4*)(A1f + (size_t)grow * K1 + lc4);
                    } else {
                        uint2 u = *(const uint2*)(A1b + (size_t)grow * K1 + lc4);
                        float2 p0 = __bfloat1622float2(*(__nv_bfloat162*)&u.x);
                        float2 p1 = __bfloat1622float2(*(__nv_bfloat162*)&u.y);
                        v = make_float4(p0.x, p0.y, p1.x, p1.y);
                    }
                } else {
                    uint2 u = *(const uint2*)(A2 + (size_t)grow * K2 + lc4);
                    float2 p0 = __bfloat1622float2(*(__nv_bfloat162*)&u.x);
                    float2 p1 = __bfloat1622float2(*(__nv_bfloat162*)&u.y);
                    float s = 1.0f / fmaxf(degraw[grow], 1.0f);
                    v = make_float4(p0.x * s, p0.y * s, p1.x * s, p1.y * s);
                }
            }
            rv[j] = v;
        }

        for (int p = 0; p < nP; p++) {
            __syncthreads();   // previous panel's mma done -> sA free
#pragma unroll
            for (int j = 0; j < 4; j++) {
                int row = lrow + j * 32;
                uint32_t* st = (uint32_t*)sA + row * AROW + (lc4 >> 1);
                st[0] = pack_bf16x2(rv[j].x, rv[j].y);
                st[1] = pack_bf16x2(rv[j].z, rv[j].w);
            }
            __syncthreads();   // panel visible

            // prefetch next panel (latency hidden by mma below)
            if (p + 1 < nP) {
                int kt = (p + 1) << 5;
#pragma unroll
                for (int j = 0; j < 4; j++) {
                    int row = lrow + j * 32;
                    int grow = bm + row;
                    float4 v = make_float4(0.f, 0.f, 0.f, 0.f);
                    if (grow < M) {
                        if (kt < K1) {
                            if (A1f) {
                                v = *(const float4*)(A1f + (size_t)grow * K1 + kt + lc4);
                            } else {
                                uint2 u = *(const uint2*)(A1b + (size_t)grow * K1 + kt + lc4);
                                float2 p0 = __bfloat1622float2(*(__nv_bfloat162*)&u.x);
                                float2 p1 = __bfloat1622float2(*(__nv_bfloat162*)&u.y);
                                v = make_float4(p0.x, p0.y, p1.x, p1.y);
                            }
                        } else {
                            int kp = kt - K1;
                            uint2 u = *(const uint2*)(A2 + (size_t)grow * K2 + kp + lc4);
                            float2 p0 = __bfloat1622float2(*(__nv_bfloat162*)&u.x);
                            float2 p1 = __bfloat1622float2(*(__nv_bfloat162*)&u.y);
                            float s = 1.0f / fmaxf(degraw[grow], 1.0f);
                            v = make_float4(p0.x * s, p0.y * s, p1.x * s, p1.y * s);
                        }
                    }
                    rv[j] = v;
                }
            }

            const uint32_t* aB = (const uint32_t*)sA;
#pragma unroll
            for (int ks = 0; ks < 2; ks++) {
                int kst = p * 2 + ks;
                uint2 bf[8];
                const uint2* wf = ((const uint2*)sW) + ((size_t)kst * 16 + (wn >> 3)) * 32 + lane;
#pragma unroll
                for (int j = 0; j < 8; j++) bf[j] = wf[j * 32];

#pragma unroll
                for (int mt = 0; mt < 2; mt++) {
                    int r = wm + mt * 16 + (lane >> 2);
                    int c = ks * 8 + (lane & 3);
                    uint32_t a0 = aB[r * AROW + c];
                    uint32_t a1 = aB[(r + 8) * AROW + c];
                    uint32_t a2 = aB[r * AROW + c + 4];
                    uint32_t a3 = aB[(r + 8) * AROW + c + 4];
#pragma unroll
                    for (int nt = 0; nt < 8; nt++)
                        mma_bf16(acc[mt][nt], a0, a1, a2, a3, bf[nt].x, bf[nt].y);
                }
            }
        }

        // epilogue: bias + relu; optional fp32 / bf16 stores
#pragma unroll
        for (int mt = 0; mt < 2; mt++) {
            int r0 = bm + wm + mt * 16 + (lane >> 2);
#pragma unroll
            for (int nt = 0; nt < 8; nt++) {
                int col = wn + nt * 8 + (lane & 3) * 2;
                float b0 = sB[col], b1 = sB[col + 1];
                float v0 = acc[mt][nt][0] + b0;
                float v1 = acc[mt][nt][1] + b1;
                float v2 = acc[mt][nt][2] + b0;
                float v3 = acc[mt][nt][3] + b1;
                if (act) {
                    v0 = fmaxf(v0, 0.f); v1 = fmaxf(v1, 0.f);
                    v2 = fmaxf(v2, 0.f); v3 = fmaxf(v3, 0.f);
                }
                if (r0 < M) {
                    if (Cf)   *(float2*)(Cf + (size_t)r0 * 128 + col) = make_float2(v0, v1);
                    if (Cb16) *(uint32_t*)(Cb16 + (size_t)r0 * 128 + col) = pack_bf16x2(v0, v1);
                }
                if (r0 + 8 < M) {
                    if (Cf)   *(float2*)(Cf + (size_t)(r0 + 8) * 128 + col) = make_float2(v2, v3);
                    if (Cb16) *(uint32_t*)(Cb16 + (size_t)(r0 + 8) * 128 + col) = pack_bf16x2(v2, v3);
                }
            }
        }

        // fused zero of aggregation rows owned by this CTA (reads all done)
        if (zeroAgg) {
            for (int i = t; i < 128 * 16; i += 256) {
                int row = bm + (i >> 4);
                if (row < M)
                    ((uint4*)(zeroAgg + (size_t)row * 128))[i & 15] =
                        make_uint4(0u, 0u, 0u, 0u);
            }
        }
    }
}

// -------- dist path layer0: y0 = relu(e[N,5] @ W0[5,128] + b0) --------
__global__ void dist0_kernel(const float* __restrict__ e, const float* __restrict__ W0,
                             const float* __restrict__ b0, float* __restrict__ out, int n) {
    __shared__ float sW[5 * 128];
    __shared__ float sb[128];
    int t = threadIdx.x;  // 128
    for (int i = t; i < 5 * 128; i += 128) sW[i] = W0[i];
    sb[t] = b0[t];
    __syncthreads();
    for (long long nd = blockIdx.x; nd < n; nd += gridDim.x) {
        const float* ev = e + nd * 5;
        float v = sb[t];
        v += ev[0] * sW[0 * 128 + t];
        v += ev[1] * sW[1 * 128 + t];
        v += ev[2] * sW[2 * 128 + t];
        v += ev[3] * sW[3 * 128 + t];
        v += ev[4] * sW[4 * 128 + t];
        out[nd * 128 + t] = fmaxf(v, 0.f);
    }
}

extern "C" void kernel_launch(void* const* d_in, const int* in_sizes, int n_in,
                              void* d_out, int out_size) {
    const float* x          = (const float*)d_in[0];
    const void*  ei         = d_in[1];
    const float* eattr      = (const float*)d_in[2];
    const float* pre_W      = (const float*)d_in[3];
    const float* pre_b      = (const float*)d_in[4];
    const float* c1_Ws      = (const float*)d_in[5];
    const float* c1_Wn      = (const float*)d_in[6];
    const float* c1_b       = (const float*)d_in[7];
    const float* c2_Ws      = (const float*)d_in[8];
    const float* c2_Wn      = (const float*)d_in[9];
    const float* c2_b       = (const float*)d_in[10];
    const float* nodepost_W = (const float*)d_in[11];
    const float* nodepost_b = (const float*)d_in[12];
    const float* d_W0       = (const float*)d_in[13];
    const float* d_b0       = (const float*)d_in[14];
    const float* d_W1       = (const float*)d_in[15];
    const float* d_b1       = (const float*)d_in[16];
    const float* d_W2       = (const float*)d_in[17];
    const float* d_b2       = (const float*)d_in[18];
    const float* d_W3       = (const float*)d_in[19];
    const float* d_b3       = (const float*)d_in[20];
    const float* final_W    = (const float*)d_in[21];
    const float* final_b    = (const float*)d_in[22];
    float* out = (float*)d_out;

    int n = in_sizes[0] / FIN;
    long long E = (long long)in_sizes[1] / 2;

    float *bufA, *bufB, *bufC, *deg, *wbuf, *vfin;
    __nv_bfloat16 *hb16, *aggb16;
    cudaGetSymbolAddress((void**)&bufA, g_bufA);
    cudaGetSymbolAddress((void**)&bufB, g_bufB);
    cudaGetSymbolAddress((void**)&bufC, g_bufC);
    cudaGetSymbolAddress((void**)&deg, g_deg);
    cudaGetSymbolAddress((void**)&wbuf, g_wbuf);
    cudaGetSymbolAddress((void**)&vfin, g_vfin);
    cudaGetSymbolAddress((void**)&hb16, g_hb16);
    cudaGetSymbolAddress((void**)&aggb16, g_aggb16);

    // fragment buffer layout (uint2 fragments; sizes in floats)
    float* f_pre  = wbuf;                  // K=256 -> 16384 floats
    float* f_c1s  = wbuf + 16384;          // K=128 -> 8192 each
    float* f_c1n  = f_c1s + 8192;
    float* f_c2s  = f_c1n + 8192;
    float* f_c2n  = f_c2s + 8192;
    float* f_d1   = f_c2n + 8192;
    float* f_d2   = f_d1 + 8192;

    const int SMEM_K256 = (256 * 64 + ABUF + 128) * 4;  // ~76 KB
    const int SMEM_K128 = (128 * 64 + ABUF + 128) * 4;  // ~43 KB
    cudaFuncSetAttribute(tc_gemm, cudaFuncAttributeMaxDynamicSharedMemorySize, SMEM_K256);

    const int nSM = 148;   // B200 (sm_100a)
    int nMB = (n + 127) / 128;
    int gemm_grid = nSM < nMB ? nSM : nMB;
    int gemm_grid2 = (2 * nSM) < nMB ? (2 * nSM) : nMB;

    int scat_grid = (int)((E + 15) / 16);

    detect_idx64_kernel<<<1, 1024>>>((const unsigned int*)ei);

    // weight fragment prep: ONE launch for 7 weights (np_W, d_W3 folded away)
    {
        dim3 g(32, 7);
        prepW_all<<<g, 256>>>(pre_W, c1_Ws, c1_Wn, c2_Ws, c2_Wn, d_W1, d_W2, wbuf);
    }
    prep_final<<<1, 128>>>(nodepost_W, nodepost_b, d_W3, d_b3, final_W, final_b, vfin);

    zero_kernel<<<(int)((n / 4 + 255) / 256) + 1, 256>>>(deg, (n + 3) / 4);
    deg_kernel<<<(int)((E + 255) / 256), 256>>>(ei, E);
    // deginv folded into tc_gemm (1/max(deg,1) at scale-load)

    // ---- dist path first: y0 -> bufB, y1 -> bufC, y2 -> bufB ----
    dist0_kernel<<<2048, 128>>>(eattr, d_W0, d_b0, bufB, n);
    tc_gemm<<<gemm_grid2, 256, SMEM_K128>>>(bufB, nullptr, H, f_d1, nullptr, 0, nullptr,
                                            nullptr, d_b1, bufC, nullptr, nullptr, n, 1);
    tc_gemm<<<gemm_grid2, 256, SMEM_K128>>>(bufC, nullptr, H, f_d2, nullptr, 0, nullptr,
                                            nullptr, d_b2, bufB, nullptr, nullptr, n, 1);
    // bufB = y2, kept alive to the end

    // ---- feat path (all hidden states bf16-only; fp32 intermediates dropped) ----
    // pre: h0 = x @ pre_W + pre_b -> hb16 (bf16); epilogue zeroes aggb16 rows
    tc_gemm<<<gemm_grid, 256, SMEM_K256>>>(x, nullptr, FIN, f_pre, nullptr, 0, nullptr,
                                           nullptr, pre_b, nullptr, hb16, aggb16, n, 0);

    // agg1 = scatter_b16(h0) -> aggb16
    scatter_b16_kernel<<<scat_grid, 256>>>(hb16, aggb16, ei, E);

    // h1 = relu(h0@c1_Ws + (1/deg)*agg1@c1_Wn + b) -> hb16 in place; re-zero aggb16
    tc_gemm<<<gemm_grid, 256, SMEM_K256>>>(nullptr, hb16, H, f_c1s, aggb16, H, f_c1n,
                                           deg, c1_b, nullptr, hb16, aggb16, n, 1);

    // agg2 = scatter_b16(h1) -> aggb16
    scatter_b16_kernel<<<scat_grid, 256>>>(hb16, aggb16, ei, E);

    // h2 = relu(h1@c2_Ws + (1/deg)*agg2@c2_Wn + b) -> bufA (fp32 for final dot)
    tc_gemm<<<gemm_grid, 256, SMEM_K256>>>(nullptr, hb16, H, f_c2s, aggb16, H, f_c2n,
                                           deg, c2_b, bufA, nullptr, nullptr, n, 1);

    // fused final: out = sigmoid(h2.v1 + y2.v2 + c)
    final_fused_kernel<<<(n + 7) / 8, 256>>>(bufA, bufB, vfin, out, n);
}